// round 3
// baseline (speedup 1.0000x reference)
#include <cuda_runtime.h>
#include <cstdint>

// ---------------------------------------------------------------------------
// Problem constants
// ---------------------------------------------------------------------------
#define BATCH      2048
#define MSEQ       64
#define STATE_DIM  32
#define CONTROL_DIM 8
#define EMBED_DIM  96
#define LATENT_DIM 128
#define HIDDEN     512
#define ROWS_XNEXT (BATCH * MSEQ)            // 131072
#define ROWS_TOTAL (BATCH + ROWS_XNEXT)      // 133120

// ---------------------------------------------------------------------------
// Scratch (no cudaMalloc allowed) — __device__ globals
// ---------------------------------------------------------------------------
__device__ float g_H1[(size_t)ROWS_TOTAL * HIDDEN];   // 272.6 MB
__device__ float g_H2[(size_t)ROWS_TOTAL * HIDDEN];   // 272.6 MB
__device__ float g_E [(size_t)ROWS_TOTAL * EMBED_DIM]; // 51.1 MB

// ---------------------------------------------------------------------------
// Packed f32x2 FMA (Blackwell FFMA2): 2 fp32 FMAs per issue, 2x scalar FFMA
// ---------------------------------------------------------------------------
__device__ __forceinline__ float2 ffma2(float a, float2 b, float2 c) {
    float2 aa = make_float2(a, a);
    unsigned long long A = *reinterpret_cast<unsigned long long*>(&aa);
    unsigned long long B = *reinterpret_cast<unsigned long long*>(&b);
    unsigned long long C = *reinterpret_cast<unsigned long long*>(&c);
    asm("fma.rn.f32x2 %0, %1, %2, %0;" : "+l"(C) : "l"(A), "l"(B));
    return *reinterpret_cast<float2*>(&C);
}

// ---------------------------------------------------------------------------
// SGEMM: C[M,N] = act(A[M,K] @ B[K,N] + bias[N])
// 128x128 block tile, BK=8, 256 threads, 8x8 per thread, FFMA2 inner loop.
// Mrows % 128 == 0 always holds here; N may be < 128 (layer4 N=96) -> guarded.
// ---------------------------------------------------------------------------
#define BM 128
#define BN 128
#define BKK 8

template<bool RELU>
__global__ __launch_bounds__(256, 2)
void sgemm_kernel(const float* __restrict__ Ag, const float* __restrict__ Bg,
                  const float* __restrict__ bias, float* __restrict__ Cg,
                  int Mrows, int N, int K)
{
    __shared__ float As[BKK][BM];
    __shared__ float Bs[BKK][BN];

    const int tid  = threadIdx.x;
    const int row0 = blockIdx.y * BM;
    const int col0 = blockIdx.x * BN;

    // A tile loader: one float4 per thread (128 rows x 8 cols)
    const int a_r = tid >> 1;            // 0..127
    const int a_c = (tid & 1) * 4;       // 0 or 4
    // B tile loader: one float4 per thread (8 rows x 128 cols)
    const int b_r = tid >> 5;            // 0..7
    const int b_c = (tid & 31) * 4;      // 0..124

    const int tx = tid & 15;             // col group
    const int ty = tid >> 4;             // row group

    float2 acc[8][4];
    #pragma unroll
    for (int i = 0; i < 8; i++)
        #pragma unroll
        for (int j = 0; j < 4; j++)
            acc[i][j] = make_float2(0.f, 0.f);

    const float* Aptr = Ag + (size_t)(row0 + a_r) * K + a_c;
    const bool  bcol_ok = (col0 + b_c) < N;
    const float* Bptr = Bg + (size_t)b_r * N + col0 + b_c;

    for (int kt = 0; kt < K; kt += BKK) {
        float4 av = *(const float4*)(Aptr);
        Aptr += BKK;
        float4 bv = bcol_ok ? *(const float4*)(Bptr) : make_float4(0.f, 0.f, 0.f, 0.f);
        Bptr += (size_t)BKK * N;

        As[a_c + 0][a_r] = av.x;
        As[a_c + 1][a_r] = av.y;
        As[a_c + 2][a_r] = av.z;
        As[a_c + 3][a_r] = av.w;
        *(float4*)&Bs[b_r][b_c] = bv;
        __syncthreads();

        #pragma unroll
        for (int k = 0; k < BKK; k++) {
            float4 a0 = *(const float4*)&As[k][ty * 8];
            float4 a1 = *(const float4*)&As[k][ty * 8 + 4];
            float4 b0 = *(const float4*)&Bs[k][tx * 8];
            float4 b1 = *(const float4*)&Bs[k][tx * 8 + 4];
            float  a[8] = {a0.x, a0.y, a0.z, a0.w, a1.x, a1.y, a1.z, a1.w};
            float2 b[4] = {make_float2(b0.x, b0.y), make_float2(b0.z, b0.w),
                           make_float2(b1.x, b1.y), make_float2(b1.z, b1.w)};
            #pragma unroll
            for (int i = 0; i < 8; i++)
                #pragma unroll
                for (int j = 0; j < 4; j++)
                    acc[i][j] = ffma2(a[i], b[j], acc[i][j]);
        }
        __syncthreads();
    }

    // Epilogue: bias + optional relu; N-guarded (N even, pairs never straddle)
    #pragma unroll
    for (int i = 0; i < 8; i++) {
        const int r = row0 + ty * 8 + i;
        #pragma unroll
        for (int j = 0; j < 4; j++) {
            const int c = col0 + tx * 8 + j * 2;
            if (c < N) {
                float2 v = acc[i][j];
                v.x += bias[c];
                v.y += bias[c + 1];
                if (RELU) { v.x = fmaxf(v.x, 0.f); v.y = fmaxf(v.y, 0.f); }
                *(float2*)&Cg[(size_t)r * N + c] = v;
            }
        }
    }
}

// ---------------------------------------------------------------------------
// z_target assembly: zt[r, 0:32] = x_next[r], zt[r, 32:128] = E[2048 + r]
// One float4 per thread.
// ---------------------------------------------------------------------------
__global__ void ztarget_kernel(const float* __restrict__ x_next,
                               const float* __restrict__ E_xnext,  // E + 2048*96
                               float* __restrict__ zt)
{
    const size_t idx = (size_t)blockIdx.x * blockDim.x + threadIdx.x;
    const size_t total = (size_t)ROWS_XNEXT * (LATENT_DIM / 4);
    if (idx >= total) return;
    const size_t r = idx >> 5;       // row
    const int    q = (int)(idx & 31); // float4 slot within row (32 per row)
    float4 v;
    if (q < STATE_DIM / 4)
        v = ((const float4*)x_next)[r * (STATE_DIM / 4) + q];
    else
        v = ((const float4*)E_xnext)[r * (EMBED_DIM / 4) + (q - STATE_DIM / 4)];
    ((float4*)zt)[r * (LATENT_DIM / 4) + q] = v;
}

// ---------------------------------------------------------------------------
// Scan: z_{i+1} = z_i @ A + u_i @ Bmat, 64 steps.
// 8 batch rows per block (256 thr); each warp owns one row; thread j owns
// latent dims 4j..4j+3. A/Bmat read as float4 LDG (L1-resident: 64KB+4KB).
// z lives in warp-private smem -> __syncwarp only.
// ---------------------------------------------------------------------------
#define SCAN_ROWS 8
__global__ __launch_bounds__(256)
void scan_kernel(const float* __restrict__ x_k, const float* __restrict__ u_seq,
                 const float* __restrict__ Amat, const float* __restrict__ Bmat,
                 const float* __restrict__ E,     // encoder rows for x_k (first 2048)
                 float* __restrict__ z_pred, float* __restrict__ x_pred)
{
    __shared__ float zsh[SCAN_ROWS][LATENT_DIM];
    __shared__ float ush[SCAN_ROWS][CONTROL_DIM];

    const int tid = threadIdx.x;
    const int lr  = tid >> 5;        // local row 0..7
    const int j   = tid & 31;        // lane
    const int b   = blockIdx.x * SCAN_ROWS + lr;
    const int d0  = j * 4;           // first owned latent dim

    // init z_k = [x_k, encode(x_k)]
    float4 z;
    if (d0 < STATE_DIM) z = *(const float4*)(x_k + (size_t)b * STATE_DIM + d0);
    else                z = *(const float4*)(E   + (size_t)b * EMBED_DIM + (d0 - STATE_DIM));
    zsh[lr][d0 + 0] = z.x; zsh[lr][d0 + 1] = z.y;
    zsh[lr][d0 + 2] = z.z; zsh[lr][d0 + 3] = z.w;
    if (j < CONTROL_DIM)
        ush[lr][j] = u_seq[((size_t)b * MSEQ + 0) * CONTROL_DIM + j];
    __syncwarp();

    for (int i = 0; i < MSEQ; i++) {
        float2 acc01 = make_float2(0.f, 0.f);
        float2 acc23 = make_float2(0.f, 0.f);

        #pragma unroll
        for (int c = 0; c < CONTROL_DIM; c++) {
            const float uc = ush[lr][c];
            float4 brow = *(const float4*)(Bmat + (size_t)c * LATENT_DIM + d0);
            acc01 = ffma2(uc, make_float2(brow.x, brow.y), acc01);
            acc23 = ffma2(uc, make_float2(brow.z, brow.w), acc23);
        }
        #pragma unroll 32
        for (int k = 0; k < LATENT_DIM; k++) {
            const float zk = zsh[lr][k];
            float4 arow = *(const float4*)(Amat + (size_t)k * LATENT_DIM + d0);
            acc01 = ffma2(zk, make_float2(arow.x, arow.y), acc01);
            acc23 = ffma2(zk, make_float2(arow.z, arow.w), acc23);
        }
        __syncwarp();  // all reads of zsh/ush done before overwrite

        zsh[lr][d0 + 0] = acc01.x; zsh[lr][d0 + 1] = acc01.y;
        zsh[lr][d0 + 2] = acc23.x; zsh[lr][d0 + 3] = acc23.y;
        if (j < CONTROL_DIM && i + 1 < MSEQ)
            ush[lr][j] = u_seq[((size_t)b * MSEQ + (i + 1)) * CONTROL_DIM + j];

        const size_t orow = (size_t)b * MSEQ + i;
        float4 out = make_float4(acc01.x, acc01.y, acc23.x, acc23.y);
        *(float4*)(z_pred + orow * LATENT_DIM + d0) = out;
        if (d0 < STATE_DIM)
            *(float4*)(x_pred + orow * STATE_DIM + d0) = out;
        __syncwarp();  // writes visible before next iter's reads
    }
}

// ---------------------------------------------------------------------------
// kernel_launch
// Inputs: 0:x_k 1:u_seq 2:x_next_seq 3:W1 4:b1 5:W2 6:b2 7:W3 8:b3
//         9:Wo 10:bo 11:A 12:Bmat
// Output: [z_pred (B,M,128) | x_pred (B,M,32) | z_target (B,M,128)]
// ---------------------------------------------------------------------------
extern "C" void kernel_launch(void* const* d_in, const int* in_sizes, int n_in,
                              void* d_out, int out_size)
{
    const float* x_k    = (const float*)d_in[0];
    const float* u_seq  = (const float*)d_in[1];
    const float* x_next = (const float*)d_in[2];
    const float* W1     = (const float*)d_in[3];
    const float* b1     = (const float*)d_in[4];
    const float* W2     = (const float*)d_in[5];
    const float* b2     = (const float*)d_in[6];
    const float* W3     = (const float*)d_in[7];
    const float* b3     = (const float*)d_in[8];
    const float* Wo     = (const float*)d_in[9];
    const float* bo     = (const float*)d_in[10];
    const float* Amat   = (const float*)d_in[11];
    const float* Bmat   = (const float*)d_in[12];

    float* out      = (float*)d_out;
    float* z_pred   = out;
    float* x_pred   = out + (size_t)BATCH * MSEQ * LATENT_DIM;
    float* z_target = x_pred + (size_t)BATCH * MSEQ * STATE_DIM;

    float *H1, *H2, *E;
    cudaGetSymbolAddress((void**)&H1, g_H1);
    cudaGetSymbolAddress((void**)&H2, g_H2);
    cudaGetSymbolAddress((void**)&E,  g_E);

    dim3 blk(256);

    // Layer 1 (K=32): x_k rows then x_next rows into H1
    {
        dim3 grid(HIDDEN / BN, BATCH / BM);
        sgemm_kernel<true><<<grid, blk>>>(x_k, W1, b1, H1, BATCH, HIDDEN, STATE_DIM);
    }
    {
        dim3 grid(HIDDEN / BN, ROWS_XNEXT / BM);
        sgemm_kernel<true><<<grid, blk>>>(x_next, W1, b1, H1 + (size_t)BATCH * HIDDEN,
                                          ROWS_XNEXT, HIDDEN, STATE_DIM);
    }
    // Layer 2: H1 @ W2 -> H2
    {
        dim3 grid(HIDDEN / BN, ROWS_TOTAL / BM);
        sgemm_kernel<true><<<grid, blk>>>(H1, W2, b2, H2, ROWS_TOTAL, HIDDEN, HIDDEN);
    }
    // Layer 3: H2 @ W3 -> H1 (reuse)
    {
        dim3 grid(HIDDEN / BN, ROWS_TOTAL / BM);
        sgemm_kernel<true><<<grid, blk>>>(H2, W3, b3, H1, ROWS_TOTAL, HIDDEN, HIDDEN);
    }
    // Layer 4: H1 @ Wo -> E (no relu), N=96 guarded
    {
        dim3 grid(1, ROWS_TOTAL / BM);
        sgemm_kernel<false><<<grid, blk>>>(H1, Wo, bo, E, ROWS_TOTAL, EMBED_DIM, HIDDEN);
    }
    // z_target assembly
    {
        const size_t total = (size_t)ROWS_XNEXT * (LATENT_DIM / 4);
        int nb = (int)((total + 255) / 256);
        ztarget_kernel<<<nb, 256>>>(x_next, E + (size_t)BATCH * EMBED_DIM, z_target);
    }
    // scan
    {
        dim3 grid(BATCH / SCAN_ROWS);
        scan_kernel<<<grid, blk>>>(x_k, u_seq, Amat, Bmat, E, z_pred, x_pred);
    }

    (void)in_sizes; (void)n_in; (void)out_size;
}

// round 7
// speedup vs baseline: 1.7755x; 1.7755x over previous
#include <cuda_runtime.h>
#include <cuda_bf16.h>
#include <cstdint>

// ---------------------------------------------------------------------------
// Problem constants
// ---------------------------------------------------------------------------
#define BATCH      2048
#define MSEQ       64
#define STATE_DIM  32
#define CONTROL_DIM 8
#define EMBED_DIM  96
#define LATENT_DIM 128
#define HIDDEN     512
#define ROWS_XNEXT (BATCH * MSEQ)            // 131072
#define ROWS_TOTAL (BATCH + ROWS_XNEXT)      // 133120
#define MTILES     (ROWS_TOTAL / 128)        // 1040

// ---------------------------------------------------------------------------
// Scratch (__device__ globals; no allocs allowed)
// ---------------------------------------------------------------------------
__device__ __nv_bfloat16 g_Xhi[(size_t)ROWS_TOTAL * 32];
__device__ __nv_bfloat16 g_Xlo[(size_t)ROWS_TOTAL * 32];
__device__ __nv_bfloat16 g_Hahi[(size_t)ROWS_TOTAL * HIDDEN];
__device__ __nv_bfloat16 g_Halo[(size_t)ROWS_TOTAL * HIDDEN];
__device__ __nv_bfloat16 g_Hbhi[(size_t)ROWS_TOTAL * HIDDEN];
__device__ __nv_bfloat16 g_Hblo[(size_t)ROWS_TOTAL * HIDDEN];
__device__ float         g_E  [(size_t)ROWS_TOTAL * EMBED_DIM];
__device__ __nv_bfloat16 g_W1thi[512 * 32],   g_W1tlo[512 * 32];    // [N][K]
__device__ __nv_bfloat16 g_W2thi[512 * 512],  g_W2tlo[512 * 512];
__device__ __nv_bfloat16 g_W3thi[512 * 512],  g_W3tlo[512 * 512];
__device__ __nv_bfloat16 g_Wothi[128 * 512],  g_Wotlo[128 * 512];   // padded N 96->128

// ---------------------------------------------------------------------------
// Helpers
// ---------------------------------------------------------------------------
__device__ __forceinline__ uint32_t smem_u32(const void* p) {
    uint32_t a;
    asm("{ .reg .u64 t; cvta.to.shared.u64 t, %1; cvt.u32.u64 %0, t; }"
        : "=r"(a) : "l"(p));
    return a;
}

#define CP16(dst, src) \
    asm volatile("cp.async.cg.shared.global [%0], [%1], 16;" \
                 :: "r"(dst), "l"(src))
#define CP_COMMIT() asm volatile("cp.async.commit_group;")
#define CP_WAIT(n)  asm volatile("cp.async.wait_group %0;" :: "n"(n))

__device__ __forceinline__ void ldsm4(uint32_t* d, uint32_t addr) {
    asm volatile("ldmatrix.sync.aligned.m8n8.x4.shared.b16 {%0,%1,%2,%3}, [%4];"
                 : "=r"(d[0]), "=r"(d[1]), "=r"(d[2]), "=r"(d[3]) : "r"(addr));
}
__device__ __forceinline__ void mma16816(float* c, const uint32_t* a,
                                         uint32_t b0, uint32_t b1) {
    asm volatile(
        "mma.sync.aligned.m16n8k16.row.col.f32.bf16.bf16.f32 "
        "{%0,%1,%2,%3}, {%4,%5,%6,%7}, {%8,%9}, {%0,%1,%2,%3};"
        : "+f"(c[0]), "+f"(c[1]), "+f"(c[2]), "+f"(c[3])
        : "r"(a[0]), "r"(a[1]), "r"(a[2]), "r"(a[3]), "r"(b0), "r"(b1));
}

__device__ __forceinline__ void split_bf16(float v, __nv_bfloat16& h, __nv_bfloat16& l) {
    h = __float2bfloat16(v);
    l = __float2bfloat16(v - __bfloat162float(h));
}
__device__ __forceinline__ void split_pack(float v0, float v1,
                                           uint32_t& hi, uint32_t& lo) {
    __nv_bfloat16 h0, l0, h1, l1;
    split_bf16(v0, h0, l0);
    split_bf16(v1, h1, l1);
    hi = (uint32_t)__bfloat16_as_ushort(h0) | ((uint32_t)__bfloat16_as_ushort(h1) << 16);
    lo = (uint32_t)__bfloat16_as_ushort(l0) | ((uint32_t)__bfloat16_as_ushort(l1) << 16);
}

// ---------------------------------------------------------------------------
// bf16 mma.sync GEMM, 3-pass hi/lo split, fp32 accumulate.
// C[128 x 128 tile] = act(A @ B^T + bias)
// A: [Mrows][ldA] hi/lo bf16 K-major. B: [Nrows][ldB] hi/lo bf16 K-major.
// B is K-major => B fragments come from PLAIN (non-trans) ldmatrix, with
// register pairing (r0,r2) / (r1,r3) for the low/high n8 blocks.
// K consumed in KB blocks of 32. Smem rows padded 64B -> 80B (conflict-free
// ldmatrix: granule stride 5 is odd -> 8 phases cover 8 distinct positions).
// ---------------------------------------------------------------------------
#define TILE_B  10240          // 128 rows * 80 bytes
#define STG_B   (4 * TILE_B)   // Ah, Al, Bh, Bl per stage

template<int KB, int STAGES, bool RELU, bool SPLIT_OUT>
__global__ __launch_bounds__(256, 1)
void gemm_mma(const __nv_bfloat16* __restrict__ Ahi, const __nv_bfloat16* __restrict__ Alo,
              int ldA,
              const __nv_bfloat16* __restrict__ Bhi, const __nv_bfloat16* __restrict__ Blo,
              int ldB,
              const float* __restrict__ bias,
              __nv_bfloat16* __restrict__ Chi, __nv_bfloat16* __restrict__ Clo,
              float* __restrict__ Cf, int ldC, int Nlim)
{
    extern __shared__ __align__(128) uint8_t dsm[];
    const uint32_t sbase = smem_u32(dsm);

    const int tid  = threadIdx.x;
    const int wid  = tid >> 5;
    const int lane = tid & 31;
    const int row0 = blockIdx.y * 128;
    const int n0   = blockIdx.x * 128;

    const int m_base = (wid >> 2) * 64;   // 0 or 64
    const int n_base = (wid & 3) * 32;    // 0,32,64,96

    // per-lane ldmatrix base offsets within a tile (same form for A and B:
    // lanes 0-15 -> rows base..base+15 at k-bytes 0, lanes 16-31 -> +16B)
    const uint32_t aoff = (uint32_t)(m_base + (lane & 15)) * 80 + ((lane >> 4) << 4);
    const uint32_t boff = (uint32_t)(n_base + (lane & 15)) * 80 + ((lane >> 4) << 4);

    float acc[4][4][4];
    #pragma unroll
    for (int f = 0; f < 4; f++)
        #pragma unroll
        for (int g = 0; g < 4; g++)
            #pragma unroll
            for (int e = 0; e < 4; e++)
                acc[f][g][e] = 0.f;

    auto load_kb = [&](int kb, int st) {
        const uint32_t sa = sbase + st * STG_B;
        #pragma unroll
        for (int t = 0; t < 2; t++) {
            int q = tid + t * 256;       // 0..511
            int r = q >> 2, c = q & 3;
            uint32_t so = (uint32_t)r * 80 + c * 16;
            size_t ga = (size_t)(row0 + r) * ldA + kb * 32 + c * 8;
            size_t gb = (size_t)(n0 + r) * ldB + kb * 32 + c * 8;
            CP16(sa + so,              Ahi + ga);
            CP16(sa + TILE_B + so,     Alo + ga);
            CP16(sa + 2 * TILE_B + so, Bhi + gb);
            CP16(sa + 3 * TILE_B + so, Blo + gb);
        }
    };

    auto compute_st = [&](int st) {
        const uint32_t sa = sbase + st * STG_B;
        #pragma unroll
        for (int ks = 0; ks < 2; ks++) {
            uint32_t ah[4][4], al[4][4], bh[2][4], bl[2][4];
            #pragma unroll
            for (int f = 0; f < 4; f++) {
                ldsm4(ah[f], sa + aoff + f * (16 * 80) + ks * 32);
                ldsm4(al[f], sa + TILE_B + aoff + f * (16 * 80) + ks * 32);
            }
            #pragma unroll
            for (int p = 0; p < 2; p++) {
                ldsm4(bh[p], sa + 2 * TILE_B + boff + p * (16 * 80) + ks * 32);
                ldsm4(bl[p], sa + 3 * TILE_B + boff + p * (16 * 80) + ks * 32);
            }
            // Fragment pairing for K-major B via non-trans ldmatrix over
            // n16 x k16: r0=(n0-7,k0-7) r1=(n8-15,k0-7) r2=(n0-7,k8-15)
            // r3=(n8-15,k8-15). n8 block s uses (r_s, r_{s+2}).
            #pragma unroll
            for (int f = 0; f < 4; f++)
                #pragma unroll
                for (int g = 0; g < 4; g++) {
                    const int p = g >> 1, s = g & 1;
                    mma16816(acc[f][g], ah[f], bh[p][s], bh[p][s + 2]);
                    mma16816(acc[f][g], ah[f], bl[p][s], bl[p][s + 2]);
                    mma16816(acc[f][g], al[f], bh[p][s], bh[p][s + 2]);
                }
        }
    };

    // prologue
    #pragma unroll
    for (int s = 0; s < STAGES - 1; s++) {
        if (s < KB) load_kb(s, s);
        CP_COMMIT();
    }
    // mainloop
    for (int kb = 0; kb < KB; kb++) {
        CP_WAIT(STAGES - 2);
        __syncthreads();
        const int nkb = kb + STAGES - 1;
        if (nkb < KB) load_kb(nkb, nkb % STAGES);
        CP_COMMIT();
        compute_st(kb % STAGES);
    }

    // epilogue
    #pragma unroll
    for (int f = 0; f < 4; f++) {
        const int rg = row0 + m_base + f * 16 + (lane >> 2);
        #pragma unroll
        for (int g = 0; g < 4; g++) {
            const int c = n0 + n_base + g * 8 + (lane & 3) * 2;
            if (c < Nlim) {
                const float b0 = bias[c], b1 = bias[c + 1];
                float v00 = acc[f][g][0] + b0, v01 = acc[f][g][1] + b1;
                float v10 = acc[f][g][2] + b0, v11 = acc[f][g][3] + b1;
                if (RELU) {
                    v00 = fmaxf(v00, 0.f); v01 = fmaxf(v01, 0.f);
                    v10 = fmaxf(v10, 0.f); v11 = fmaxf(v11, 0.f);
                }
                if (SPLIT_OUT) {
                    uint32_t hi0, lo0, hi1, lo1;
                    split_pack(v00, v01, hi0, lo0);
                    split_pack(v10, v11, hi1, lo1);
                    *(uint32_t*)(Chi + (size_t)rg * ldC + c)       = hi0;
                    *(uint32_t*)(Clo + (size_t)rg * ldC + c)       = lo0;
                    *(uint32_t*)(Chi + (size_t)(rg + 8) * ldC + c) = hi1;
                    *(uint32_t*)(Clo + (size_t)(rg + 8) * ldC + c) = lo1;
                } else {
                    Cf[(size_t)rg * ldC + c]           = v00;
                    Cf[(size_t)rg * ldC + c + 1]       = v01;
                    Cf[(size_t)(rg + 8) * ldC + c]     = v10;
                    Cf[(size_t)(rg + 8) * ldC + c + 1] = v11;
                }
            }
        }
    }
}

// ---------------------------------------------------------------------------
// Converters
// ---------------------------------------------------------------------------
__global__ void conv_x_kernel(const float* __restrict__ xk, const float* __restrict__ xn,
                              __nv_bfloat16* __restrict__ hi, __nv_bfloat16* __restrict__ lo)
{
    int i = blockIdx.x * 256 + threadIdx.x;
    if (i >= ROWS_TOTAL * 32) return;
    int row = i >> 5, c = i & 31;
    float v = (row < BATCH) ? xk[row * 32 + c]
                            : xn[(size_t)(row - BATCH) * 32 + c];
    __nv_bfloat16 h, l;
    split_bf16(v, h, l);
    size_t o = (size_t)row * 32 + c;
    hi[o] = h; lo[o] = l;
}

// W: [K][N] row-major  ->  hi/lo: [Npad][K] (K-major), zero-pad n >= N
__global__ void conv_w_kernel(const float* __restrict__ W,
                              __nv_bfloat16* __restrict__ hi, __nv_bfloat16* __restrict__ lo,
                              int K, int N, int Npad)
{
    int i = blockIdx.x * 256 + threadIdx.x;
    if (i >= Npad * K) return;
    int k = i / Npad, n = i % Npad;     // coalesced read over n
    float v = (n < N) ? W[(size_t)k * N + n] : 0.f;
    __nv_bfloat16 h, l;
    split_bf16(v, h, l);
    hi[(size_t)n * K + k] = h;
    lo[(size_t)n * K + k] = l;
}

// ---------------------------------------------------------------------------
// z_target assembly + scan (unchanged from passing R3 kernel)
// ---------------------------------------------------------------------------
__device__ __forceinline__ float2 ffma2(float a, float2 b, float2 c) {
    float2 aa = make_float2(a, a);
    unsigned long long A = *reinterpret_cast<unsigned long long*>(&aa);
    unsigned long long B = *reinterpret_cast<unsigned long long*>(&b);
    unsigned long long C = *reinterpret_cast<unsigned long long*>(&c);
    asm("fma.rn.f32x2 %0, %1, %2, %0;" : "+l"(C) : "l"(A), "l"(B));
    return *reinterpret_cast<float2*>(&C);
}

__global__ void ztarget_kernel(const float* __restrict__ x_next,
                               const float* __restrict__ E_xnext,
                               float* __restrict__ zt)
{
    const size_t idx = (size_t)blockIdx.x * blockDim.x + threadIdx.x;
    const size_t total = (size_t)ROWS_XNEXT * (LATENT_DIM / 4);
    if (idx >= total) return;
    const size_t r = idx >> 5;
    const int    q = (int)(idx & 31);
    float4 v;
    if (q < STATE_DIM / 4)
        v = ((const float4*)x_next)[r * (STATE_DIM / 4) + q];
    else
        v = ((const float4*)E_xnext)[r * (EMBED_DIM / 4) + (q - STATE_DIM / 4)];
    ((float4*)zt)[r * (LATENT_DIM / 4) + q] = v;
}

#define SCAN_ROWS 8
__global__ __launch_bounds__(256)
void scan_kernel(const float* __restrict__ x_k, const float* __restrict__ u_seq,
                 const float* __restrict__ Amat, const float* __restrict__ Bmat,
                 const float* __restrict__ E,
                 float* __restrict__ z_pred, float* __restrict__ x_pred)
{
    __shared__ float zsh[SCAN_ROWS][LATENT_DIM];
    __shared__ float ush[SCAN_ROWS][CONTROL_DIM];

    const int tid = threadIdx.x;
    const int lr  = tid >> 5;
    const int j   = tid & 31;
    const int b   = blockIdx.x * SCAN_ROWS + lr;
    const int d0  = j * 4;

    float4 z;
    if (d0 < STATE_DIM) z = *(const float4*)(x_k + (size_t)b * STATE_DIM + d0);
    else                z = *(const float4*)(E   + (size_t)b * EMBED_DIM + (d0 - STATE_DIM));
    zsh[lr][d0 + 0] = z.x; zsh[lr][d0 + 1] = z.y;
    zsh[lr][d0 + 2] = z.z; zsh[lr][d0 + 3] = z.w;
    if (j < CONTROL_DIM)
        ush[lr][j] = u_seq[((size_t)b * MSEQ + 0) * CONTROL_DIM + j];
    __syncwarp();

    for (int i = 0; i < MSEQ; i++) {
        float2 acc01 = make_float2(0.f, 0.f);
        float2 acc23 = make_float2(0.f, 0.f);

        #pragma unroll
        for (int c = 0; c < CONTROL_DIM; c++) {
            const float uc = ush[lr][c];
            float4 brow = *(const float4*)(Bmat + (size_t)c * LATENT_DIM + d0);
            acc01 = ffma2(uc, make_float2(brow.x, brow.y), acc01);
            acc23 = ffma2(uc, make_float2(brow.z, brow.w), acc23);
        }
        #pragma unroll 32
        for (int k = 0; k < LATENT_DIM; k++) {
            const float zk = zsh[lr][k];
            float4 arow = *(const float4*)(Amat + (size_t)k * LATENT_DIM + d0);
            acc01 = ffma2(zk, make_float2(arow.x, arow.y), acc01);
            acc23 = ffma2(zk, make_float2(arow.z, arow.w), acc23);
        }
        __syncwarp();

        zsh[lr][d0 + 0] = acc01.x; zsh[lr][d0 + 1] = acc01.y;
        zsh[lr][d0 + 2] = acc23.x; zsh[lr][d0 + 3] = acc23.y;
        if (j < CONTROL_DIM && i + 1 < MSEQ)
            ush[lr][j] = u_seq[((size_t)b * MSEQ + (i + 1)) * CONTROL_DIM + j];

        const size_t orow = (size_t)b * MSEQ + i;
        float4 out = make_float4(acc01.x, acc01.y, acc23.x, acc23.y);
        *(float4*)(z_pred + orow * LATENT_DIM + d0) = out;
        if (d0 < STATE_DIM)
            *(float4*)(x_pred + orow * STATE_DIM + d0) = out;
        __syncwarp();
    }
}

// ---------------------------------------------------------------------------
// kernel_launch
// Inputs: 0:x_k 1:u_seq 2:x_next_seq 3:W1 4:b1 5:W2 6:b2 7:W3 8:b3
//         9:Wo 10:bo 11:A 12:Bmat
// ---------------------------------------------------------------------------
extern "C" void kernel_launch(void* const* d_in, const int* in_sizes, int n_in,
                              void* d_out, int out_size)
{
    const float* x_k    = (const float*)d_in[0];
    const float* u_seq  = (const float*)d_in[1];
    const float* x_next = (const float*)d_in[2];
    const float* W1     = (const float*)d_in[3];
    const float* b1     = (const float*)d_in[4];
    const float* W2     = (const float*)d_in[5];
    const float* b2     = (const float*)d_in[6];
    const float* W3     = (const float*)d_in[7];
    const float* b3     = (const float*)d_in[8];
    const float* Wo     = (const float*)d_in[9];
    const float* bo     = (const float*)d_in[10];
    const float* Amat   = (const float*)d_in[11];
    const float* Bmat   = (const float*)d_in[12];

    float* out      = (float*)d_out;
    float* z_pred   = out;
    float* x_pred   = out + (size_t)BATCH * MSEQ * LATENT_DIM;
    float* z_target = x_pred + (size_t)BATCH * MSEQ * STATE_DIM;

    __nv_bfloat16 *Xhi, *Xlo, *Hahi, *Halo, *Hbhi, *Hblo;
    __nv_bfloat16 *W1thi, *W1tlo, *W2thi, *W2tlo, *W3thi, *W3tlo, *Wothi, *Wotlo;
    float* E;
    cudaGetSymbolAddress((void**)&Xhi,  g_Xhi);  cudaGetSymbolAddress((void**)&Xlo,  g_Xlo);
    cudaGetSymbolAddress((void**)&Hahi, g_Hahi); cudaGetSymbolAddress((void**)&Halo, g_Halo);
    cudaGetSymbolAddress((void**)&Hbhi, g_Hbhi); cudaGetSymbolAddress((void**)&Hblo, g_Hblo);
    cudaGetSymbolAddress((void**)&W1thi, g_W1thi); cudaGetSymbolAddress((void**)&W1tlo, g_W1tlo);
    cudaGetSymbolAddress((void**)&W2thi, g_W2thi); cudaGetSymbolAddress((void**)&W2tlo, g_W2tlo);
    cudaGetSymbolAddress((void**)&W3thi, g_W3thi); cudaGetSymbolAddress((void**)&W3tlo, g_W3tlo);
    cudaGetSymbolAddress((void**)&Wothi, g_Wothi); cudaGetSymbolAddress((void**)&Wotlo, g_Wotlo);
    cudaGetSymbolAddress((void**)&E, g_E);

    const int SMEM2 = 2 * STG_B;   // 81920
    const int SMEM3 = 3 * STG_B;   // 122880
    cudaFuncSetAttribute(gemm_mma<1, 2, true,  true >,
                         cudaFuncAttributeMaxDynamicSharedMemorySize, SMEM2);
    cudaFuncSetAttribute(gemm_mma<16, 3, true,  true >,
                         cudaFuncAttributeMaxDynamicSharedMemorySize, SMEM3);
    cudaFuncSetAttribute(gemm_mma<16, 3, false, false>,
                         cudaFuncAttributeMaxDynamicSharedMemorySize, SMEM3);

    // split conversions
    conv_x_kernel<<<(ROWS_TOTAL * 32 + 255) / 256, 256>>>(x_k, x_next, Xhi, Xlo);
    conv_w_kernel<<<(512 * 32 + 255) / 256, 256>>>(W1, W1thi, W1tlo, 32, 512, 512);
    conv_w_kernel<<<(512 * 512 + 255) / 256, 256>>>(W2, W2thi, W2tlo, 512, 512, 512);
    conv_w_kernel<<<(512 * 512 + 255) / 256, 256>>>(W3, W3thi, W3tlo, 512, 512, 512);
    conv_w_kernel<<<(128 * 512 + 255) / 256, 256>>>(Wo, Wothi, Wotlo, 512, 96, 128);

    // encoder MLP on tensor cores (mma.sync bf16, 3-pass split)
    gemm_mma<1, 2, true, true><<<dim3(4, MTILES), 256, SMEM2>>>(
        Xhi, Xlo, 32, W1thi, W1tlo, 32, b1, Hahi, Halo, nullptr, 512, 512);
    gemm_mma<16, 3, true, true><<<dim3(4, MTILES), 256, SMEM3>>>(
        Hahi, Halo, 512, W2thi, W2tlo, 512, b2, Hbhi, Hblo, nullptr, 512, 512);
    gemm_mma<16, 3, true, true><<<dim3(4, MTILES), 256, SMEM3>>>(
        Hbhi, Hblo, 512, W3thi, W3tlo, 512, b3, Hahi, Halo, nullptr, 512, 512);
    gemm_mma<16, 3, false, false><<<dim3(1, MTILES), 256, SMEM3>>>(
        Hahi, Halo, 512, Wothi, Wotlo, 512, bo, nullptr, nullptr, E, 96, 96);

    // outputs
    {
        const size_t total = (size_t)ROWS_XNEXT * (LATENT_DIM / 4);
        int nb = (int)((total + 255) / 256);
        ztarget_kernel<<<nb, 256>>>(x_next, E + (size_t)BATCH * EMBED_DIM, z_target);
    }
    scan_kernel<<<BATCH / SCAN_ROWS, 256>>>(x_k, u_seq, Amat, Bmat, E, z_pred, x_pred);

    (void)in_sizes; (void)n_in; (void)out_size;
}

// round 8
// speedup vs baseline: 2.0700x; 1.1658x over previous
#include <cuda_runtime.h>
#include <cuda_bf16.h>
#include <cstdint>

// ---------------------------------------------------------------------------
// Problem constants
// ---------------------------------------------------------------------------
#define BATCH      2048
#define MSEQ       64
#define STATE_DIM  32
#define CONTROL_DIM 8
#define EMBED_DIM  96
#define LATENT_DIM 128
#define HIDDEN     512
#define ROWS_XNEXT (BATCH * MSEQ)            // 131072
#define ROWS_TOTAL (BATCH + ROWS_XNEXT)      // 133120
#define MTILES     (ROWS_TOTAL / 128)        // 1040

// ---------------------------------------------------------------------------
// Scratch (__device__ globals; no allocs allowed)
// ---------------------------------------------------------------------------
__device__ __nv_bfloat16 g_Xhi[(size_t)ROWS_TOTAL * 32];
__device__ __nv_bfloat16 g_Xlo[(size_t)ROWS_TOTAL * 32];
__device__ __nv_bfloat16 g_Hahi[(size_t)ROWS_TOTAL * HIDDEN];
__device__ __nv_bfloat16 g_Halo[(size_t)ROWS_TOTAL * HIDDEN];
__device__ __nv_bfloat16 g_Hbhi[(size_t)ROWS_TOTAL * HIDDEN];
__device__ __nv_bfloat16 g_Hblo[(size_t)ROWS_TOTAL * HIDDEN];
__device__ float         g_E  [(size_t)ROWS_TOTAL * EMBED_DIM];
__device__ __nv_bfloat16 g_W1thi[512 * 32],   g_W1tlo[512 * 32];    // [N][K]
__device__ __nv_bfloat16 g_W2thi[512 * 512],  g_W2tlo[512 * 512];
__device__ __nv_bfloat16 g_W3thi[512 * 512],  g_W3tlo[512 * 512];
__device__ __nv_bfloat16 g_Wothi[128 * 512],  g_Wotlo[128 * 512];   // padded N 96->128

// ---------------------------------------------------------------------------
// Helpers
// ---------------------------------------------------------------------------
__device__ __forceinline__ uint32_t smem_u32(const void* p) {
    uint32_t a;
    asm("{ .reg .u64 t; cvta.to.shared.u64 t, %1; cvt.u32.u64 %0, t; }"
        : "=r"(a) : "l"(p));
    return a;
}

#define CP16(dst, src) \
    asm volatile("cp.async.cg.shared.global [%0], [%1], 16;" \
                 :: "r"(dst), "l"(src))
#define CP_COMMIT() asm volatile("cp.async.commit_group;")
#define CP_WAIT(n)  asm volatile("cp.async.wait_group %0;" :: "n"(n))

__device__ __forceinline__ void ldsm4(uint32_t* d, uint32_t addr) {
    asm volatile("ldmatrix.sync.aligned.m8n8.x4.shared.b16 {%0,%1,%2,%3}, [%4];"
                 : "=r"(d[0]), "=r"(d[1]), "=r"(d[2]), "=r"(d[3]) : "r"(addr));
}
__device__ __forceinline__ void mma16816(float* c, const uint32_t* a,
                                         uint32_t b0, uint32_t b1) {
    asm volatile(
        "mma.sync.aligned.m16n8k16.row.col.f32.bf16.bf16.f32 "
        "{%0,%1,%2,%3}, {%4,%5,%6,%7}, {%8,%9}, {%0,%1,%2,%3};"
        : "+f"(c[0]), "+f"(c[1]), "+f"(c[2]), "+f"(c[3])
        : "r"(a[0]), "r"(a[1]), "r"(a[2]), "r"(a[3]), "r"(b0), "r"(b1));
}

__device__ __forceinline__ void split_bf16(float v, __nv_bfloat16& h, __nv_bfloat16& l) {
    h = __float2bfloat16(v);
    l = __float2bfloat16(v - __bfloat162float(h));
}
__device__ __forceinline__ void split_pack(float v0, float v1,
                                           uint32_t& hi, uint32_t& lo) {
    __nv_bfloat16 h0, l0, h1, l1;
    split_bf16(v0, h0, l0);
    split_bf16(v1, h1, l1);
    hi = (uint32_t)__bfloat16_as_ushort(h0) | ((uint32_t)__bfloat16_as_ushort(h1) << 16);
    lo = (uint32_t)__bfloat16_as_ushort(l0) | ((uint32_t)__bfloat16_as_ushort(l1) << 16);
}

// ---------------------------------------------------------------------------
// bf16 mma.sync GEMM, 3-pass hi/lo split, fp32 accumulate.
// C[128 x 128 tile] = act(A @ B^T + bias)
// A: [Mrows][ldA] hi/lo bf16 K-major. B: [Nrows][ldB] hi/lo bf16 K-major.
// B fragments via PLAIN (non-trans) ldmatrix, pairing (r_s, r_{s+2}).
// MMA issue is PASS-MAJOR: all Ah*Bh, then Ah*Bl, then Al*Bh -> same-acc
// dependent MMAs are 16 apart (>= HMMA latency), no RAW serialization.
// 2 cp.async stages (80KB smem) -> 2 blocks/SM for latency hiding.
// ---------------------------------------------------------------------------
#define TILE_B  10240          // 128 rows * 80 bytes
#define STG_B   (4 * TILE_B)   // Ah, Al, Bh, Bl per stage

template<int KB, bool RELU, bool SPLIT_OUT>
__global__ __launch_bounds__(256, 2)
void gemm_mma(const __nv_bfloat16* __restrict__ Ahi, const __nv_bfloat16* __restrict__ Alo,
              int ldA,
              const __nv_bfloat16* __restrict__ Bhi, const __nv_bfloat16* __restrict__ Blo,
              int ldB,
              const float* __restrict__ bias,
              __nv_bfloat16* __restrict__ Chi, __nv_bfloat16* __restrict__ Clo,
              float* __restrict__ Cf, int ldC, int Nlim)
{
    extern __shared__ __align__(128) uint8_t dsm[];
    const uint32_t sbase = smem_u32(dsm);

    const int tid  = threadIdx.x;
    const int wid  = tid >> 5;
    const int lane = tid & 31;
    const int row0 = blockIdx.y * 128;
    const int n0   = blockIdx.x * 128;

    const int m_base = (wid >> 2) * 64;   // 0 or 64
    const int n_base = (wid & 3) * 32;    // 0,32,64,96

    // per-lane ldmatrix base offsets (lanes 0-15: rows, lanes 16-31: +16B)
    const uint32_t aoff = (uint32_t)(m_base + (lane & 15)) * 80 + ((lane >> 4) << 4);
    const uint32_t boff = (uint32_t)(n_base + (lane & 15)) * 80 + ((lane >> 4) << 4);

    float acc[4][4][4];
    #pragma unroll
    for (int f = 0; f < 4; f++)
        #pragma unroll
        for (int g = 0; g < 4; g++)
            #pragma unroll
            for (int e = 0; e < 4; e++)
                acc[f][g][e] = 0.f;

    auto load_kb = [&](int kb, int st) {
        const uint32_t sa = sbase + st * STG_B;
        #pragma unroll
        for (int t = 0; t < 2; t++) {
            int q = tid + t * 256;       // 0..511
            int r = q >> 2, c = q & 3;
            uint32_t so = (uint32_t)r * 80 + c * 16;
            size_t ga = (size_t)(row0 + r) * ldA + kb * 32 + c * 8;
            size_t gb = (size_t)(n0 + r) * ldB + kb * 32 + c * 8;
            CP16(sa + so,              Ahi + ga);
            CP16(sa + TILE_B + so,     Alo + ga);
            CP16(sa + 2 * TILE_B + so, Bhi + gb);
            CP16(sa + 3 * TILE_B + so, Blo + gb);
        }
    };

    auto compute_st = [&](int st) {
        const uint32_t sa = sbase + st * STG_B;
        #pragma unroll
        for (int ks = 0; ks < 2; ks++) {
            uint32_t ah[4][4], bh[2][4], bl[2][4];
            #pragma unroll
            for (int f = 0; f < 4; f++)
                ldsm4(ah[f], sa + aoff + f * (16 * 80) + ks * 32);
            #pragma unroll
            for (int p = 0; p < 2; p++) {
                ldsm4(bh[p], sa + 2 * TILE_B + boff + p * (16 * 80) + ks * 32);
                ldsm4(bl[p], sa + 3 * TILE_B + boff + p * (16 * 80) + ks * 32);
            }
            // pass 1: Ah*Bh
            #pragma unroll
            for (int f = 0; f < 4; f++)
                #pragma unroll
                for (int g = 0; g < 4; g++) {
                    const int p = g >> 1, s = g & 1;
                    mma16816(acc[f][g], ah[f], bh[p][s], bh[p][s + 2]);
                }
            // pass 2: Ah*Bl
            #pragma unroll
            for (int f = 0; f < 4; f++)
                #pragma unroll
                for (int g = 0; g < 4; g++) {
                    const int p = g >> 1, s = g & 1;
                    mma16816(acc[f][g], ah[f], bl[p][s], bl[p][s + 2]);
                }
            // pass 3: Al*Bh (Al loaded late to cap register liveness)
            uint32_t al[4][4];
            #pragma unroll
            for (int f = 0; f < 4; f++)
                ldsm4(al[f], sa + TILE_B + aoff + f * (16 * 80) + ks * 32);
            #pragma unroll
            for (int f = 0; f < 4; f++)
                #pragma unroll
                for (int g = 0; g < 4; g++) {
                    const int p = g >> 1, s = g & 1;
                    mma16816(acc[f][g], al[f], bh[p][s], bh[p][s + 2]);
                }
        }
    };

    // prologue: fill stage 0
    load_kb(0, 0);
    CP_COMMIT();
    // mainloop (2-stage double buffer)
    for (int kb = 0; kb < KB; kb++) {
        const int s = kb & 1;
        CP_WAIT(0);
        __syncthreads();
        if (kb + 1 < KB) {
            load_kb(kb + 1, s ^ 1);
            CP_COMMIT();
        }
        compute_st(s);
    }

    // epilogue
    #pragma unroll
    for (int f = 0; f < 4; f++) {
        const int rg = row0 + m_base + f * 16 + (lane >> 2);
        #pragma unroll
        for (int g = 0; g < 4; g++) {
            const int c = n0 + n_base + g * 8 + (lane & 3) * 2;
            if (c < Nlim) {
                const float b0 = bias[c], b1 = bias[c + 1];
                float v00 = acc[f][g][0] + b0, v01 = acc[f][g][1] + b1;
                float v10 = acc[f][g][2] + b0, v11 = acc[f][g][3] + b1;
                if (RELU) {
                    v00 = fmaxf(v00, 0.f); v01 = fmaxf(v01, 0.f);
                    v10 = fmaxf(v10, 0.f); v11 = fmaxf(v11, 0.f);
                }
                if (SPLIT_OUT) {
                    uint32_t hi0, lo0, hi1, lo1;
                    split_pack(v00, v01, hi0, lo0);
                    split_pack(v10, v11, hi1, lo1);
                    *(uint32_t*)(Chi + (size_t)rg * ldC + c)       = hi0;
                    *(uint32_t*)(Clo + (size_t)rg * ldC + c)       = lo0;
                    *(uint32_t*)(Chi + (size_t)(rg + 8) * ldC + c) = hi1;
                    *(uint32_t*)(Clo + (size_t)(rg + 8) * ldC + c) = lo1;
                } else {
                    Cf[(size_t)rg * ldC + c]           = v00;
                    Cf[(size_t)rg * ldC + c + 1]       = v01;
                    Cf[(size_t)(rg + 8) * ldC + c]     = v10;
                    Cf[(size_t)(rg + 8) * ldC + c + 1] = v11;
                }
            }
        }
    }
}

// ---------------------------------------------------------------------------
// Converters
// ---------------------------------------------------------------------------
__global__ void conv_x_kernel(const float* __restrict__ xk, const float* __restrict__ xn,
                              __nv_bfloat16* __restrict__ hi, __nv_bfloat16* __restrict__ lo)
{
    int i = blockIdx.x * 256 + threadIdx.x;
    if (i >= ROWS_TOTAL * 32) return;
    int row = i >> 5, c = i & 31;
    float v = (row < BATCH) ? xk[row * 32 + c]
                            : xn[(size_t)(row - BATCH) * 32 + c];
    __nv_bfloat16 h, l;
    split_bf16(v, h, l);
    size_t o = (size_t)row * 32 + c;
    hi[o] = h; lo[o] = l;
}

// W: [K][N] row-major  ->  hi/lo: [Npad][K] (K-major), zero-pad n >= N
__global__ void conv_w_kernel(const float* __restrict__ W,
                              __nv_bfloat16* __restrict__ hi, __nv_bfloat16* __restrict__ lo,
                              int K, int N, int Npad)
{
    int i = blockIdx.x * 256 + threadIdx.x;
    if (i >= Npad * K) return;
    int k = i / Npad, n = i % Npad;     // coalesced read over n
    float v = (n < N) ? W[(size_t)k * N + n] : 0.f;
    __nv_bfloat16 h, l;
    split_bf16(v, h, l);
    hi[(size_t)n * K + k] = h;
    lo[(size_t)n * K + k] = l;
}

// ---------------------------------------------------------------------------
// z_target assembly + scan (unchanged from passing R3 kernel)
// ---------------------------------------------------------------------------
__device__ __forceinline__ float2 ffma2(float a, float2 b, float2 c) {
    float2 aa = make_float2(a, a);
    unsigned long long A = *reinterpret_cast<unsigned long long*>(&aa);
    unsigned long long B = *reinterpret_cast<unsigned long long*>(&b);
    unsigned long long C = *reinterpret_cast<unsigned long long*>(&c);
    asm("fma.rn.f32x2 %0, %1, %2, %0;" : "+l"(C) : "l"(A), "l"(B));
    return *reinterpret_cast<float2*>(&C);
}

__global__ void ztarget_kernel(const float* __restrict__ x_next,
                               const float* __restrict__ E_xnext,
                               float* __restrict__ zt)
{
    const size_t idx = (size_t)blockIdx.x * blockDim.x + threadIdx.x;
    const size_t total = (size_t)ROWS_XNEXT * (LATENT_DIM / 4);
    if (idx >= total) return;
    const size_t r = idx >> 5;
    const int    q = (int)(idx & 31);
    float4 v;
    if (q < STATE_DIM / 4)
        v = ((const float4*)x_next)[r * (STATE_DIM / 4) + q];
    else
        v = ((const float4*)E_xnext)[r * (EMBED_DIM / 4) + (q - STATE_DIM / 4)];
    ((float4*)zt)[r * (LATENT_DIM / 4) + q] = v;
}

#define SCAN_ROWS 8
__global__ __launch_bounds__(256)
void scan_kernel(const float* __restrict__ x_k, const float* __restrict__ u_seq,
                 const float* __restrict__ Amat, const float* __restrict__ Bmat,
                 const float* __restrict__ E,
                 float* __restrict__ z_pred, float* __restrict__ x_pred)
{
    __shared__ float zsh[SCAN_ROWS][LATENT_DIM];
    __shared__ float ush[SCAN_ROWS][CONTROL_DIM];

    const int tid = threadIdx.x;
    const int lr  = tid >> 5;
    const int j   = tid & 31;
    const int b   = blockIdx.x * SCAN_ROWS + lr;
    const int d0  = j * 4;

    float4 z;
    if (d0 < STATE_DIM) z = *(const float4*)(x_k + (size_t)b * STATE_DIM + d0);
    else                z = *(const float4*)(E   + (size_t)b * EMBED_DIM + (d0 - STATE_DIM));
    zsh[lr][d0 + 0] = z.x; zsh[lr][d0 + 1] = z.y;
    zsh[lr][d0 + 2] = z.z; zsh[lr][d0 + 3] = z.w;
    if (j < CONTROL_DIM)
        ush[lr][j] = u_seq[((size_t)b * MSEQ + 0) * CONTROL_DIM + j];
    __syncwarp();

    for (int i = 0; i < MSEQ; i++) {
        float2 acc01 = make_float2(0.f, 0.f);
        float2 acc23 = make_float2(0.f, 0.f);

        #pragma unroll
        for (int c = 0; c < CONTROL_DIM; c++) {
            const float uc = ush[lr][c];
            float4 brow = *(const float4*)(Bmat + (size_t)c * LATENT_DIM + d0);
            acc01 = ffma2(uc, make_float2(brow.x, brow.y), acc01);
            acc23 = ffma2(uc, make_float2(brow.z, brow.w), acc23);
        }
        #pragma unroll 32
        for (int k = 0; k < LATENT_DIM; k++) {
            const float zk = zsh[lr][k];
            float4 arow = *(const float4*)(Amat + (size_t)k * LATENT_DIM + d0);
            acc01 = ffma2(zk, make_float2(arow.x, arow.y), acc01);
            acc23 = ffma2(zk, make_float2(arow.z, arow.w), acc23);
        }
        __syncwarp();

        zsh[lr][d0 + 0] = acc01.x; zsh[lr][d0 + 1] = acc01.y;
        zsh[lr][d0 + 2] = acc23.x; zsh[lr][d0 + 3] = acc23.y;
        if (j < CONTROL_DIM && i + 1 < MSEQ)
            ush[lr][j] = u_seq[((size_t)b * MSEQ + (i + 1)) * CONTROL_DIM + j];

        const size_t orow = (size_t)b * MSEQ + i;
        float4 out = make_float4(acc01.x, acc01.y, acc23.x, acc23.y);
        *(float4*)(z_pred + orow * LATENT_DIM + d0) = out;
        if (d0 < STATE_DIM)
            *(float4*)(x_pred + orow * STATE_DIM + d0) = out;
        __syncwarp();
    }
}

// ---------------------------------------------------------------------------
// kernel_launch
// Inputs: 0:x_k 1:u_seq 2:x_next_seq 3:W1 4:b1 5:W2 6:b2 7:W3 8:b3
//         9:Wo 10:bo 11:A 12:Bmat
// ---------------------------------------------------------------------------
extern "C" void kernel_launch(void* const* d_in, const int* in_sizes, int n_in,
                              void* d_out, int out_size)
{
    const float* x_k    = (const float*)d_in[0];
    const float* u_seq  = (const float*)d_in[1];
    const float* x_next = (const float*)d_in[2];
    const float* W1     = (const float*)d_in[3];
    const float* b1     = (const float*)d_in[4];
    const float* W2     = (const float*)d_in[5];
    const float* b2     = (const float*)d_in[6];
    const float* W3     = (const float*)d_in[7];
    const float* b3     = (const float*)d_in[8];
    const float* Wo     = (const float*)d_in[9];
    const float* bo     = (const float*)d_in[10];
    const float* Amat   = (const float*)d_in[11];
    const float* Bmat   = (const float*)d_in[12];

    float* out      = (float*)d_out;
    float* z_pred   = out;
    float* x_pred   = out + (size_t)BATCH * MSEQ * LATENT_DIM;
    float* z_target = x_pred + (size_t)BATCH * MSEQ * STATE_DIM;

    __nv_bfloat16 *Xhi, *Xlo, *Hahi, *Halo, *Hbhi, *Hblo;
    __nv_bfloat16 *W1thi, *W1tlo, *W2thi, *W2tlo, *W3thi, *W3tlo, *Wothi, *Wotlo;
    float* E;
    cudaGetSymbolAddress((void**)&Xhi,  g_Xhi);  cudaGetSymbolAddress((void**)&Xlo,  g_Xlo);
    cudaGetSymbolAddress((void**)&Hahi, g_Hahi); cudaGetSymbolAddress((void**)&Halo, g_Halo);
    cudaGetSymbolAddress((void**)&Hbhi, g_Hbhi); cudaGetSymbolAddress((void**)&Hblo, g_Hblo);
    cudaGetSymbolAddress((void**)&W1thi, g_W1thi); cudaGetSymbolAddress((void**)&W1tlo, g_W1tlo);
    cudaGetSymbolAddress((void**)&W2thi, g_W2thi); cudaGetSymbolAddress((void**)&W2tlo, g_W2tlo);
    cudaGetSymbolAddress((void**)&W3thi, g_W3thi); cudaGetSymbolAddress((void**)&W3tlo, g_W3tlo);
    cudaGetSymbolAddress((void**)&Wothi, g_Wothi); cudaGetSymbolAddress((void**)&Wotlo, g_Wotlo);
    cudaGetSymbolAddress((void**)&E, g_E);

    const int SMEM2 = 2 * STG_B;   // 81920 -> 2 blocks/SM
    cudaFuncSetAttribute(gemm_mma<1,  true,  true >,
                         cudaFuncAttributeMaxDynamicSharedMemorySize, SMEM2);
    cudaFuncSetAttribute(gemm_mma<16, true,  true >,
                         cudaFuncAttributeMaxDynamicSharedMemorySize, SMEM2);
    cudaFuncSetAttribute(gemm_mma<16, false, false>,
                         cudaFuncAttributeMaxDynamicSharedMemorySize, SMEM2);

    // split conversions
    conv_x_kernel<<<(ROWS_TOTAL * 32 + 255) / 256, 256>>>(x_k, x_next, Xhi, Xlo);
    conv_w_kernel<<<(512 * 32 + 255) / 256, 256>>>(W1, W1thi, W1tlo, 32, 512, 512);
    conv_w_kernel<<<(512 * 512 + 255) / 256, 256>>>(W2, W2thi, W2tlo, 512, 512, 512);
    conv_w_kernel<<<(512 * 512 + 255) / 256, 256>>>(W3, W3thi, W3tlo, 512, 512, 512);
    conv_w_kernel<<<(128 * 512 + 255) / 256, 256>>>(Wo, Wothi, Wotlo, 512, 96, 128);

    // encoder MLP on tensor cores (mma.sync bf16, 3-pass split, pass-major)
    gemm_mma<1, true, true><<<dim3(4, MTILES), 256, SMEM2>>>(
        Xhi, Xlo, 32, W1thi, W1tlo, 32, b1, Hahi, Halo, nullptr, 512, 512);
    gemm_mma<16, true, true><<<dim3(4, MTILES), 256, SMEM2>>>(
        Hahi, Halo, 512, W2thi, W2tlo, 512, b2, Hbhi, Hblo, nullptr, 512, 512);
    gemm_mma<16, true, true><<<dim3(4, MTILES), 256, SMEM2>>>(
        Hbhi, Hblo, 512, W3thi, W3tlo, 512, b3, Hahi, Halo, nullptr, 512, 512);
    gemm_mma<16, false, false><<<dim3(1, MTILES), 256, SMEM2>>>(
        Hahi, Halo, 512, Wothi, Wotlo, 512, bo, nullptr, nullptr, E, 96, 96);

    // outputs
    {
        const size_t total = (size_t)ROWS_XNEXT * (LATENT_DIM / 4);
        int nb = (int)((total + 255) / 256);
        ztarget_kernel<<<nb, 256>>>(x_next, E + (size_t)BATCH * EMBED_DIM, z_target);
    }
    scan_kernel<<<BATCH / SCAN_ROWS, 256>>>(x_k, u_seq, Amat, Bmat, E, z_pred, x_pred);

    (void)in_sizes; (void)n_in; (void)out_size;
}

// round 9
// speedup vs baseline: 2.4942x; 1.2050x over previous
#include <cuda_runtime.h>
#include <cuda_fp16.h>
#include <cstdint>

// ---------------------------------------------------------------------------
// Problem constants
// ---------------------------------------------------------------------------
#define BATCH      2048
#define MSEQ       64
#define STATE_DIM  32
#define CONTROL_DIM 8
#define EMBED_DIM  96
#define LATENT_DIM 128
#define HIDDEN     512
#define ROWS_XNEXT (BATCH * MSEQ)            // 131072
#define ROWS_TOTAL (BATCH + ROWS_XNEXT)      // 133120
#define MTILES     (ROWS_TOTAL / 128)        // 1040

// ---------------------------------------------------------------------------
// Scratch (__device__ globals; no allocs allowed) — all fp16 now
// ---------------------------------------------------------------------------
__device__ __half g_Xhi[(size_t)ROWS_TOTAL * 32];
__device__ __half g_Xlo[(size_t)ROWS_TOTAL * 32];
__device__ __half g_Hahi[(size_t)ROWS_TOTAL * HIDDEN];
__device__ __half g_Halo[(size_t)ROWS_TOTAL * HIDDEN];
__device__ __half g_Hbhi[(size_t)ROWS_TOTAL * HIDDEN];
__device__ __half g_Hblo[(size_t)ROWS_TOTAL * HIDDEN];
__device__ float  g_E  [(size_t)ROWS_TOTAL * EMBED_DIM];
__device__ __half g_W1thi[512 * 32],   g_W1tlo[512 * 32];    // [N][K]
__device__ __half g_W2thi[512 * 512],  g_W2tlo[512 * 512];
__device__ __half g_W3thi[512 * 512],  g_W3tlo[512 * 512];
__device__ __half g_Wothi[128 * 512],  g_Wotlo[128 * 512];   // padded N 96->128

// ---------------------------------------------------------------------------
// Helpers
// ---------------------------------------------------------------------------
__device__ __forceinline__ uint32_t smem_u32(const void* p) {
    uint32_t a;
    asm("{ .reg .u64 t; cvta.to.shared.u64 t, %1; cvt.u32.u64 %0, t; }"
        : "=r"(a) : "l"(p));
    return a;
}

#define CP16(dst, src) \
    asm volatile("cp.async.cg.shared.global [%0], [%1], 16;" \
                 :: "r"(dst), "l"(src))
#define CP_COMMIT() asm volatile("cp.async.commit_group;")
#define CP_WAIT(n)  asm volatile("cp.async.wait_group %0;" :: "n"(n))

__device__ __forceinline__ void ldsm4(uint32_t* d, uint32_t addr) {
    asm volatile("ldmatrix.sync.aligned.m8n8.x4.shared.b16 {%0,%1,%2,%3}, [%4];"
                 : "=r"(d[0]), "=r"(d[1]), "=r"(d[2]), "=r"(d[3]) : "r"(addr));
}
__device__ __forceinline__ void mma16816(float* c, const uint32_t* a,
                                         uint32_t b0, uint32_t b1) {
    asm volatile(
        "mma.sync.aligned.m16n8k16.row.col.f32.f16.f16.f32 "
        "{%0,%1,%2,%3}, {%4,%5,%6,%7}, {%8,%9}, {%0,%1,%2,%3};"
        : "+f"(c[0]), "+f"(c[1]), "+f"(c[2]), "+f"(c[3])
        : "r"(a[0]), "r"(a[1]), "r"(a[2]), "r"(a[3]), "r"(b0), "r"(b1));
}

__device__ __forceinline__ void split_h(float v, __half& h, __half& l) {
    h = __float2half(v);
    l = __float2half(v - __half2float(h));
}
__device__ __forceinline__ void split_pack(float v0, float v1,
                                           uint32_t& hi, uint32_t& lo) {
    __half h0, l0, h1, l1;
    split_h(v0, h0, l0);
    split_h(v1, h1, l1);
    hi = (uint32_t)__half_as_ushort(h0) | ((uint32_t)__half_as_ushort(h1) << 16);
    lo = (uint32_t)__half_as_ushort(l0) | ((uint32_t)__half_as_ushort(l1) << 16);
}

// ---------------------------------------------------------------------------
// fp16 mma.sync GEMM, NPASS-split, fp32 accumulate.
// C[128 x 128 tile] = act(A @ B^T + bias)
// A: [Mrows][ldA] hi/lo fp16 K-major. B: [Nrows][ldB] hi(/lo) fp16 K-major.
// NPASS==3: C = Ah*Bh + Ah*Bl + Al*Bh   (rel err ~2^-22)
// NPASS==2: C = Ah*Bh + Al*Bh = A*Bh    (rel err ~u_fp16/sqrt(3) ~ 2.8e-4)
// B fragments via PLAIN (non-trans) ldmatrix, pairing (r_s, r_{s+2}).
// Pass-major MMA order: same-acc dependent MMAs 16 apart.
// Stage tiles: [Ah][Al][Bh]([Bl]) of 10240B each; STAGES-deep cp.async ring
// with always-commit (empty tail groups keep wait_group counts exact).
// ---------------------------------------------------------------------------
#define TILE_B  10240          // 128 rows * 80 bytes

template<int KB, int STAGES, int NPASS, bool RELU, bool SPLIT_OUT>
__global__ __launch_bounds__(256, 2)
void gemm_mma(const __half* __restrict__ Ahi, const __half* __restrict__ Alo,
              int ldA,
              const __half* __restrict__ Bhi, const __half* __restrict__ Blo,
              int ldB,
              const float* __restrict__ bias,
              __half* __restrict__ Chi, __half* __restrict__ Clo,
              float* __restrict__ Cf, int ldC, int Nlim)
{
    constexpr int NTILES = NPASS + 1;          // Ah, Al, Bh (+Bl)
    constexpr int STG    = NTILES * TILE_B;

    extern __shared__ __align__(128) uint8_t dsm[];
    const uint32_t sbase = smem_u32(dsm);

    const int tid  = threadIdx.x;
    const int wid  = tid >> 5;
    const int lane = tid & 31;
    const int row0 = blockIdx.y * 128;
    const int n0   = blockIdx.x * 128;

    const int m_base = (wid >> 2) * 64;   // 0 or 64
    const int n_base = (wid & 3) * 32;    // 0,32,64,96

    const uint32_t aoff = (uint32_t)(m_base + (lane & 15)) * 80 + ((lane >> 4) << 4);
    const uint32_t boff = (uint32_t)(n_base + (lane & 15)) * 80 + ((lane >> 4) << 4);

    float acc[4][4][4];
    #pragma unroll
    for (int f = 0; f < 4; f++)
        #pragma unroll
        for (int g = 0; g < 4; g++)
            #pragma unroll
            for (int e = 0; e < 4; e++)
                acc[f][g][e] = 0.f;

    auto load_kb = [&](int kb, int st) {
        const uint32_t sa = sbase + st * STG;
        #pragma unroll
        for (int t = 0; t < 2; t++) {
            int q = tid + t * 256;       // 0..511
            int r = q >> 2, c = q & 3;
            uint32_t so = (uint32_t)r * 80 + c * 16;
            size_t ga = (size_t)(row0 + r) * ldA + kb * 32 + c * 8;
            size_t gb = (size_t)(n0 + r) * ldB + kb * 32 + c * 8;
            CP16(sa + so,              Ahi + ga);
            CP16(sa + TILE_B + so,     Alo + ga);
            CP16(sa + 2 * TILE_B + so, Bhi + gb);
            if (NPASS == 3)
                CP16(sa + 3 * TILE_B + so, Blo + gb);
        }
    };

    auto compute_st = [&](int st) {
        const uint32_t sa = sbase + st * STG;
        #pragma unroll
        for (int ks = 0; ks < 2; ks++) {
            uint32_t ah[4][4], bh[2][4];
            #pragma unroll
            for (int f = 0; f < 4; f++)
                ldsm4(ah[f], sa + aoff + f * (16 * 80) + ks * 32);
            #pragma unroll
            for (int p = 0; p < 2; p++)
                ldsm4(bh[p], sa + 2 * TILE_B + boff + p * (16 * 80) + ks * 32);
            // pass 1: Ah*Bh
            #pragma unroll
            for (int f = 0; f < 4; f++)
                #pragma unroll
                for (int g = 0; g < 4; g++) {
                    const int p = g >> 1, s = g & 1;
                    mma16816(acc[f][g], ah[f], bh[p][s], bh[p][s + 2]);
                }
            // pass 2 (3-pass only): Ah*Bl
            if (NPASS == 3) {
                uint32_t bl[2][4];
                #pragma unroll
                for (int p = 0; p < 2; p++)
                    ldsm4(bl[p], sa + 3 * TILE_B + boff + p * (16 * 80) + ks * 32);
                #pragma unroll
                for (int f = 0; f < 4; f++)
                    #pragma unroll
                    for (int g = 0; g < 4; g++) {
                        const int p = g >> 1, s = g & 1;
                        mma16816(acc[f][g], ah[f], bl[p][s], bl[p][s + 2]);
                    }
            }
            // final pass: Al*Bh
            uint32_t al[4][4];
            #pragma unroll
            for (int f = 0; f < 4; f++)
                ldsm4(al[f], sa + TILE_B + aoff + f * (16 * 80) + ks * 32);
            #pragma unroll
            for (int f = 0; f < 4; f++)
                #pragma unroll
                for (int g = 0; g < 4; g++) {
                    const int p = g >> 1, s = g & 1;
                    mma16816(acc[f][g], al[f], bh[p][s], bh[p][s + 2]);
                }
        }
    };

    // prologue: fill STAGES-1 stages (always commit, even if empty)
    #pragma unroll
    for (int s = 0; s < STAGES - 1; s++) {
        if (s < KB) load_kb(s, s);
        CP_COMMIT();
    }
    // mainloop
    for (int kb = 0; kb < KB; kb++) {
        CP_WAIT(STAGES - 2);
        __syncthreads();
        const int nkb = kb + STAGES - 1;
        if (nkb < KB) load_kb(nkb, nkb % STAGES);
        CP_COMMIT();                       // always: keeps group math exact
        compute_st(kb % STAGES);
    }

    // epilogue
    #pragma unroll
    for (int f = 0; f < 4; f++) {
        const int rg = row0 + m_base + f * 16 + (lane >> 2);
        #pragma unroll
        for (int g = 0; g < 4; g++) {
            const int c = n0 + n_base + g * 8 + (lane & 3) * 2;
            if (c < Nlim) {
                const float b0 = bias[c], b1 = bias[c + 1];
                float v00 = acc[f][g][0] + b0, v01 = acc[f][g][1] + b1;
                float v10 = acc[f][g][2] + b0, v11 = acc[f][g][3] + b1;
                if (RELU) {
                    v00 = fmaxf(v00, 0.f); v01 = fmaxf(v01, 0.f);
                    v10 = fmaxf(v10, 0.f); v11 = fmaxf(v11, 0.f);
                }
                if (SPLIT_OUT) {
                    uint32_t hi0, lo0, hi1, lo1;
                    split_pack(v00, v01, hi0, lo0);
                    split_pack(v10, v11, hi1, lo1);
                    *(uint32_t*)(Chi + (size_t)rg * ldC + c)       = hi0;
                    *(uint32_t*)(Clo + (size_t)rg * ldC + c)       = lo0;
                    *(uint32_t*)(Chi + (size_t)(rg + 8) * ldC + c) = hi1;
                    *(uint32_t*)(Clo + (size_t)(rg + 8) * ldC + c) = lo1;
                } else {
                    Cf[(size_t)rg * ldC + c]           = v00;
                    Cf[(size_t)rg * ldC + c + 1]       = v01;
                    Cf[(size_t)(rg + 8) * ldC + c]     = v10;
                    Cf[(size_t)(rg + 8) * ldC + c + 1] = v11;
                }
            }
        }
    }
}

// ---------------------------------------------------------------------------
// Converters (fp16 split)
// ---------------------------------------------------------------------------
__global__ void conv_x_kernel(const float* __restrict__ xk, const float* __restrict__ xn,
                              __half* __restrict__ hi, __half* __restrict__ lo)
{
    int i = blockIdx.x * 256 + threadIdx.x;
    if (i >= ROWS_TOTAL * 32) return;
    int row = i >> 5, c = i & 31;
    float v = (row < BATCH) ? xk[row * 32 + c]
                            : xn[(size_t)(row - BATCH) * 32 + c];
    __half h, l;
    split_h(v, h, l);
    size_t o = (size_t)row * 32 + c;
    hi[o] = h; lo[o] = l;
}

// W: [K][N] row-major  ->  hi/lo: [Npad][K] (K-major), zero-pad n >= N
__global__ void conv_w_kernel(const float* __restrict__ W,
                              __half* __restrict__ hi, __half* __restrict__ lo,
                              int K, int N, int Npad)
{
    int i = blockIdx.x * 256 + threadIdx.x;
    if (i >= Npad * K) return;
    int k = i / Npad, n = i % Npad;     // coalesced read over n
    float v = (n < N) ? W[(size_t)k * N + n] : 0.f;
    __half h, l;
    split_h(v, h, l);
    hi[(size_t)n * K + k] = h;
    lo[(size_t)n * K + k] = l;
}

// ---------------------------------------------------------------------------
// z_target assembly + scan (unchanged, fp32-exact)
// ---------------------------------------------------------------------------
__device__ __forceinline__ float2 ffma2(float a, float2 b, float2 c) {
    float2 aa = make_float2(a, a);
    unsigned long long A = *reinterpret_cast<unsigned long long*>(&aa);
    unsigned long long B = *reinterpret_cast<unsigned long long*>(&b);
    unsigned long long C = *reinterpret_cast<unsigned long long*>(&c);
    asm("fma.rn.f32x2 %0, %1, %2, %0;" : "+l"(C) : "l"(A), "l"(B));
    return *reinterpret_cast<float2*>(&C);
}

__global__ void ztarget_kernel(const float* __restrict__ x_next,
                               const float* __restrict__ E_xnext,
                               float* __restrict__ zt)
{
    const size_t idx = (size_t)blockIdx.x * blockDim.x + threadIdx.x;
    const size_t total = (size_t)ROWS_XNEXT * (LATENT_DIM / 4);
    if (idx >= total) return;
    const size_t r = idx >> 5;
    const int    q = (int)(idx & 31);
    float4 v;
    if (q < STATE_DIM / 4)
        v = ((const float4*)x_next)[r * (STATE_DIM / 4) + q];
    else
        v = ((const float4*)E_xnext)[r * (EMBED_DIM / 4) + (q - STATE_DIM / 4)];
    ((float4*)zt)[r * (LATENT_DIM / 4) + q] = v;
}

#define SCAN_ROWS 8
__global__ __launch_bounds__(256)
void scan_kernel(const float* __restrict__ x_k, const float* __restrict__ u_seq,
                 const float* __restrict__ Amat, const float* __restrict__ Bmat,
                 const float* __restrict__ E,
                 float* __restrict__ z_pred, float* __restrict__ x_pred)
{
    __shared__ float zsh[SCAN_ROWS][LATENT_DIM];
    __shared__ float ush[SCAN_ROWS][CONTROL_DIM];

    const int tid = threadIdx.x;
    const int lr  = tid >> 5;
    const int j   = tid & 31;
    const int b   = blockIdx.x * SCAN_ROWS + lr;
    const int d0  = j * 4;

    float4 z;
    if (d0 < STATE_DIM) z = *(const float4*)(x_k + (size_t)b * STATE_DIM + d0);
    else                z = *(const float4*)(E   + (size_t)b * EMBED_DIM + (d0 - STATE_DIM));
    zsh[lr][d0 + 0] = z.x; zsh[lr][d0 + 1] = z.y;
    zsh[lr][d0 + 2] = z.z; zsh[lr][d0 + 3] = z.w;
    if (j < CONTROL_DIM)
        ush[lr][j] = u_seq[((size_t)b * MSEQ + 0) * CONTROL_DIM + j];
    __syncwarp();

    for (int i = 0; i < MSEQ; i++) {
        float2 acc01 = make_float2(0.f, 0.f);
        float2 acc23 = make_float2(0.f, 0.f);

        #pragma unroll
        for (int c = 0; c < CONTROL_DIM; c++) {
            const float uc = ush[lr][c];
            float4 brow = *(const float4*)(Bmat + (size_t)c * LATENT_DIM + d0);
            acc01 = ffma2(uc, make_float2(brow.x, brow.y), acc01);
            acc23 = ffma2(uc, make_float2(brow.z, brow.w), acc23);
        }
        #pragma unroll 32
        for (int k = 0; k < LATENT_DIM; k++) {
            const float zk = zsh[lr][k];
            float4 arow = *(const float4*)(Amat + (size_t)k * LATENT_DIM + d0);
            acc01 = ffma2(zk, make_float2(arow.x, arow.y), acc01);
            acc23 = ffma2(zk, make_float2(arow.z, arow.w), acc23);
        }
        __syncwarp();

        zsh[lr][d0 + 0] = acc01.x; zsh[lr][d0 + 1] = acc01.y;
        zsh[lr][d0 + 2] = acc23.x; zsh[lr][d0 + 3] = acc23.y;
        if (j < CONTROL_DIM && i + 1 < MSEQ)
            ush[lr][j] = u_seq[((size_t)b * MSEQ + (i + 1)) * CONTROL_DIM + j];

        const size_t orow = (size_t)b * MSEQ + i;
        float4 out = make_float4(acc01.x, acc01.y, acc23.x, acc23.y);
        *(float4*)(z_pred + orow * LATENT_DIM + d0) = out;
        if (d0 < STATE_DIM)
            *(float4*)(x_pred + orow * STATE_DIM + d0) = out;
        __syncwarp();
    }
}

// ---------------------------------------------------------------------------
// kernel_launch
// Inputs: 0:x_k 1:u_seq 2:x_next_seq 3:W1 4:b1 5:W2 6:b2 7:W3 8:b3
//         9:Wo 10:bo 11:A 12:Bmat
// Launch order puts the big W2 GEMM at position 6 (ncu -s 5 -c 1 window).
// ---------------------------------------------------------------------------
extern "C" void kernel_launch(void* const* d_in, const int* in_sizes, int n_in,
                              void* d_out, int out_size)
{
    const float* x_k    = (const float*)d_in[0];
    const float* u_seq  = (const float*)d_in[1];
    const float* x_next = (const float*)d_in[2];
    const float* W1     = (const float*)d_in[3];
    const float* b1     = (const float*)d_in[4];
    const float* W2     = (const float*)d_in[5];
    const float* b2     = (const float*)d_in[6];
    const float* W3     = (const float*)d_in[7];
    const float* b3     = (const float*)d_in[8];
    const float* Wo     = (const float*)d_in[9];
    const float* bo     = (const float*)d_in[10];
    const float* Amat   = (const float*)d_in[11];
    const float* Bmat   = (const float*)d_in[12];

    float* out      = (float*)d_out;
    float* z_pred   = out;
    float* x_pred   = out + (size_t)BATCH * MSEQ * LATENT_DIM;
    float* z_target = x_pred + (size_t)BATCH * MSEQ * STATE_DIM;

    __half *Xhi, *Xlo, *Hahi, *Halo, *Hbhi, *Hblo;
    __half *W1thi, *W1tlo, *W2thi, *W2tlo, *W3thi, *W3tlo, *Wothi, *Wotlo;
    float* E;
    cudaGetSymbolAddress((void**)&Xhi,  g_Xhi);  cudaGetSymbolAddress((void**)&Xlo,  g_Xlo);
    cudaGetSymbolAddress((void**)&Hahi, g_Hahi); cudaGetSymbolAddress((void**)&Halo, g_Halo);
    cudaGetSymbolAddress((void**)&Hbhi, g_Hbhi); cudaGetSymbolAddress((void**)&Hblo, g_Hblo);
    cudaGetSymbolAddress((void**)&W1thi, g_W1thi); cudaGetSymbolAddress((void**)&W1tlo, g_W1tlo);
    cudaGetSymbolAddress((void**)&W2thi, g_W2thi); cudaGetSymbolAddress((void**)&W2tlo, g_W2tlo);
    cudaGetSymbolAddress((void**)&W3thi, g_W3thi); cudaGetSymbolAddress((void**)&W3tlo, g_W3tlo);
    cudaGetSymbolAddress((void**)&Wothi, g_Wothi); cudaGetSymbolAddress((void**)&Wotlo, g_Wotlo);
    cudaGetSymbolAddress((void**)&E, g_E);

    const int SMEM_P3_S2 = 2 * 4 * TILE_B;   // 81920  (3-pass, 2 stages)
    const int SMEM_P2_S3 = 3 * 3 * TILE_B;   // 92160  (2-pass, 3 stages)
    cudaFuncSetAttribute(gemm_mma<1,  2, 3, true,  true >,
                         cudaFuncAttributeMaxDynamicSharedMemorySize, SMEM_P3_S2);
    cudaFuncSetAttribute(gemm_mma<16, 3, 2, true,  true >,
                         cudaFuncAttributeMaxDynamicSharedMemorySize, SMEM_P2_S3);
    cudaFuncSetAttribute(gemm_mma<16, 2, 3, false, false>,
                         cudaFuncAttributeMaxDynamicSharedMemorySize, SMEM_P3_S2);

    // conversions needed before the first three GEMMs       (launches 1-4)
    conv_x_kernel<<<(ROWS_TOTAL * 32 + 255) / 256, 256>>>(x_k, x_next, Xhi, Xlo);
    conv_w_kernel<<<(512 * 32 + 255) / 256, 256>>>(W1, W1thi, W1tlo, 32, 512, 512);
    conv_w_kernel<<<(512 * 512 + 255) / 256, 256>>>(W2, W2thi, W2tlo, 512, 512, 512);
    conv_w_kernel<<<(512 * 512 + 255) / 256, 256>>>(W3, W3thi, W3tlo, 512, 512, 512);

    // layer1 (3-pass, K=32)                                  (launch 5)
    gemm_mma<1, 2, 3, true, true><<<dim3(4, MTILES), 256, SMEM_P3_S2>>>(
        Xhi, Xlo, 32, W1thi, W1tlo, 32, b1, Hahi, Halo, nullptr, 512, 512);
    // layer2 (2-pass fp16)                                   (launch 6 -> ncu window)
    gemm_mma<16, 3, 2, true, true><<<dim3(4, MTILES), 256, SMEM_P2_S3>>>(
        Hahi, Halo, 512, W2thi, nullptr, 512, b2, Hbhi, Hblo, nullptr, 512, 512);
    // layer3 (2-pass fp16)                                   (launch 7)
    gemm_mma<16, 3, 2, true, true><<<dim3(4, MTILES), 256, SMEM_P2_S3>>>(
        Hbhi, Hblo, 512, W3thi, nullptr, 512, b3, Hahi, Halo, nullptr, 512, 512);
    // Wo conversion + layer4 (3-pass, fp32 out)              (launches 8,9)
    conv_w_kernel<<<(128 * 512 + 255) / 256, 256>>>(Wo, Wothi, Wotlo, 512, 96, 128);
    gemm_mma<16, 2, 3, false, false><<<dim3(1, MTILES), 256, SMEM_P3_S2>>>(
        Hahi, Halo, 512, Wothi, Wotlo, 512, bo, nullptr, nullptr, E, 96, 96);

    // outputs                                                (launches 10,11)
    {
        const size_t total = (size_t)ROWS_XNEXT * (LATENT_DIM / 4);
        int nb = (int)((total + 255) / 256);
        ztarget_kernel<<<nb, 256>>>(x_next, E + (size_t)BATCH * EMBED_DIM, z_target);
    }
    scan_kernel<<<BATCH / SCAN_ROWS, 256>>>(x_k, u_seq, Amat, Bmat, E, z_pred, x_pred);

    (void)in_sizes; (void)n_in; (void)out_size;
}

// round 10
// speedup vs baseline: 3.6030x; 1.4445x over previous
#include <cuda_runtime.h>
#include <cuda_fp16.h>
#include <cstdint>

// ---------------------------------------------------------------------------
// Problem constants
// ---------------------------------------------------------------------------
#define BATCH      2048
#define MSEQ       64
#define STATE_DIM  32
#define CONTROL_DIM 8
#define EMBED_DIM  96
#define LATENT_DIM 128
#define HIDDEN     512
#define ROWS_XNEXT (BATCH * MSEQ)            // 131072
#define ROWS_TOTAL (BATCH + ROWS_XNEXT)      // 133120
#define MTILES     (ROWS_TOTAL / 128)        // 1040

// ---------------------------------------------------------------------------
// Scratch (__device__ globals; no allocs allowed)
// ---------------------------------------------------------------------------
__device__ __half g_Xhi[(size_t)ROWS_TOTAL * 32];
__device__ __half g_Xlo[(size_t)ROWS_TOTAL * 32];
__device__ __half g_Hahi[(size_t)ROWS_TOTAL * HIDDEN];   // H1 (single) / H3 hi
__device__ __half g_Halo[(size_t)ROWS_TOTAL * HIDDEN];   // H3 lo
__device__ __half g_Hbhi[(size_t)ROWS_TOTAL * HIDDEN];   // H2 (single)
__device__ float  g_E  [(size_t)ROWS_TOTAL * EMBED_DIM];
__device__ __half g_W1thi[512 * 32],   g_W1tlo[512 * 32];    // [N][K]
__device__ __half g_W2thi[512 * 512];                        // 1-pass: hi only
__device__ __half g_W3thi[512 * 512];
__device__ __half g_Wothi[128 * 512],  g_Wotlo[128 * 512];   // padded N 96->128

// ---------------------------------------------------------------------------
// Helpers
// ---------------------------------------------------------------------------
__device__ __forceinline__ uint32_t smem_u32(const void* p) {
    uint32_t a;
    asm("{ .reg .u64 t; cvta.to.shared.u64 t, %1; cvt.u32.u64 %0, t; }"
        : "=r"(a) : "l"(p));
    return a;
}

#define CP16(dst, src) \
    asm volatile("cp.async.cg.shared.global [%0], [%1], 16;" \
                 :: "r"(dst), "l"(src))
#define CP_COMMIT() asm volatile("cp.async.commit_group;")
#define CP_WAIT(n)  asm volatile("cp.async.wait_group %0;" :: "n"(n))

__device__ __forceinline__ void ldsm4(uint32_t* d, uint32_t addr) {
    asm volatile("ldmatrix.sync.aligned.m8n8.x4.shared.b16 {%0,%1,%2,%3}, [%4];"
                 : "=r"(d[0]), "=r"(d[1]), "=r"(d[2]), "=r"(d[3]) : "r"(addr));
}
__device__ __forceinline__ void mma16816(float* c, const uint32_t* a,
                                         uint32_t b0, uint32_t b1) {
    asm volatile(
        "mma.sync.aligned.m16n8k16.row.col.f32.f16.f16.f32 "
        "{%0,%1,%2,%3}, {%4,%5,%6,%7}, {%8,%9}, {%0,%1,%2,%3};"
        : "+f"(c[0]), "+f"(c[1]), "+f"(c[2]), "+f"(c[3])
        : "r"(a[0]), "r"(a[1]), "r"(a[2]), "r"(a[3]), "r"(b0), "r"(b1));
}

__device__ __forceinline__ void split_h(float v, __half& h, __half& l) {
    h = __float2half(v);
    l = __float2half(v - __half2float(h));
}
__device__ __forceinline__ void split_pack(float v0, float v1,
                                           uint32_t& hi, uint32_t& lo) {
    __half h0, l0, h1, l1;
    split_h(v0, h0, l0);
    split_h(v1, h1, l1);
    hi = (uint32_t)__half_as_ushort(h0) | ((uint32_t)__half_as_ushort(h1) << 16);
    lo = (uint32_t)__half_as_ushort(l0) | ((uint32_t)__half_as_ushort(l1) << 16);
}
__device__ __forceinline__ uint32_t pack_h2(float a, float b) {
    __half2 h = __floats2half2_rn(a, b);
    return *reinterpret_cast<uint32_t*>(&h);
}

// ---------------------------------------------------------------------------
// fp16 mma.sync GEMM, NPASS-split, fp32 accumulate.
// C[128 x 128 tile] = act(A @ B^T + bias)
// NPASS==3: C = Ah*Bh + Ah*Bl + Al*Bh   (near-exact, ~2^-22)
// NPASS==1: C = Ah*Bh                   (pure fp16 operands)
// OUTM: 0 = fp32 store, 1 = single fp16 store, 2 = hi/lo split fp16 store
// B fragments via PLAIN (non-trans) ldmatrix, pairing (r_s, r_{s+2}).
// Pass-major MMA order. STAGES-deep cp.async ring, always-commit.
// ---------------------------------------------------------------------------
#define TILE_B  10240          // 128 rows * 80 bytes

template<int KB, int STAGES, int NPASS, bool RELU, int OUTM>
__global__ __launch_bounds__(256, 2)
void gemm_mma(const __half* __restrict__ Ahi, const __half* __restrict__ Alo,
              int ldA,
              const __half* __restrict__ Bhi, const __half* __restrict__ Blo,
              int ldB,
              const float* __restrict__ bias,
              __half* __restrict__ Chi, __half* __restrict__ Clo,
              float* __restrict__ Cf, int ldC, int Nlim)
{
    constexpr int A_TILES = (NPASS == 1) ? 1 : 2;
    constexpr int B_TILES = (NPASS == 3) ? 2 : 1;
    constexpr int STG     = (A_TILES + B_TILES) * TILE_B;
    constexpr uint32_t BOFF  = A_TILES * TILE_B;            // Bh tile
    constexpr uint32_t BLOFF = (A_TILES + 1) * TILE_B;      // Bl tile (3-pass)

    extern __shared__ __align__(128) uint8_t dsm[];
    const uint32_t sbase = smem_u32(dsm);

    const int tid  = threadIdx.x;
    const int wid  = tid >> 5;
    const int lane = tid & 31;
    const int row0 = blockIdx.y * 128;
    const int n0   = blockIdx.x * 128;

    const int m_base = (wid >> 2) * 64;   // 0 or 64
    const int n_base = (wid & 3) * 32;    // 0,32,64,96

    const uint32_t aoff = (uint32_t)(m_base + (lane & 15)) * 80 + ((lane >> 4) << 4);
    const uint32_t boff = (uint32_t)(n_base + (lane & 15)) * 80 + ((lane >> 4) << 4);

    float acc[4][4][4];
    #pragma unroll
    for (int f = 0; f < 4; f++)
        #pragma unroll
        for (int g = 0; g < 4; g++)
            #pragma unroll
            for (int e = 0; e < 4; e++)
                acc[f][g][e] = 0.f;

    auto load_kb = [&](int kb, int st) {
        const uint32_t sa = sbase + st * STG;
        #pragma unroll
        for (int t = 0; t < 2; t++) {
            int q = tid + t * 256;       // 0..511
            int r = q >> 2, c = q & 3;
            uint32_t so = (uint32_t)r * 80 + c * 16;
            size_t ga = (size_t)(row0 + r) * ldA + kb * 32 + c * 8;
            size_t gb = (size_t)(n0 + r) * ldB + kb * 32 + c * 8;
            CP16(sa + so, Ahi + ga);
            if (NPASS > 1)  CP16(sa + TILE_B + so, Alo + ga);
            CP16(sa + BOFF + so, Bhi + gb);
            if (NPASS == 3) CP16(sa + BLOFF + so, Blo + gb);
        }
    };

    auto compute_st = [&](int st) {
        const uint32_t sa = sbase + st * STG;
        #pragma unroll
        for (int ks = 0; ks < 2; ks++) {
            uint32_t ah[4][4], bh[2][4];
            #pragma unroll
            for (int f = 0; f < 4; f++)
                ldsm4(ah[f], sa + aoff + f * (16 * 80) + ks * 32);
            #pragma unroll
            for (int p = 0; p < 2; p++)
                ldsm4(bh[p], sa + BOFF + boff + p * (16 * 80) + ks * 32);
            // pass 1: Ah*Bh
            #pragma unroll
            for (int f = 0; f < 4; f++)
                #pragma unroll
                for (int g = 0; g < 4; g++) {
                    const int p = g >> 1, s = g & 1;
                    mma16816(acc[f][g], ah[f], bh[p][s], bh[p][s + 2]);
                }
            // pass 2 (3-pass only): Ah*Bl
            if (NPASS == 3) {
                uint32_t bl[2][4];
                #pragma unroll
                for (int p = 0; p < 2; p++)
                    ldsm4(bl[p], sa + BLOFF + boff + p * (16 * 80) + ks * 32);
                #pragma unroll
                for (int f = 0; f < 4; f++)
                    #pragma unroll
                    for (int g = 0; g < 4; g++) {
                        const int p = g >> 1, s = g & 1;
                        mma16816(acc[f][g], ah[f], bl[p][s], bl[p][s + 2]);
                    }
            }
            // final pass (NPASS>1): Al*Bh
            if (NPASS > 1) {
                uint32_t al[4][4];
                #pragma unroll
                for (int f = 0; f < 4; f++)
                    ldsm4(al[f], sa + TILE_B + aoff + f * (16 * 80) + ks * 32);
                #pragma unroll
                for (int f = 0; f < 4; f++)
                    #pragma unroll
                    for (int g = 0; g < 4; g++) {
                        const int p = g >> 1, s = g & 1;
                        mma16816(acc[f][g], al[f], bh[p][s], bh[p][s + 2]);
                    }
            }
        }
    };

    // prologue
    #pragma unroll
    for (int s = 0; s < STAGES - 1; s++) {
        if (s < KB) load_kb(s, s);
        CP_COMMIT();
    }
    // mainloop
    for (int kb = 0; kb < KB; kb++) {
        CP_WAIT(STAGES - 2);
        __syncthreads();
        const int nkb = kb + STAGES - 1;
        if (nkb < KB) load_kb(nkb, nkb % STAGES);
        CP_COMMIT();
        compute_st(kb % STAGES);
    }

    // epilogue
    #pragma unroll
    for (int f = 0; f < 4; f++) {
        const int rg = row0 + m_base + f * 16 + (lane >> 2);
        #pragma unroll
        for (int g = 0; g < 4; g++) {
            const int c = n0 + n_base + g * 8 + (lane & 3) * 2;
            if (c < Nlim) {
                const float b0 = bias[c], b1 = bias[c + 1];
                float v00 = acc[f][g][0] + b0, v01 = acc[f][g][1] + b1;
                float v10 = acc[f][g][2] + b0, v11 = acc[f][g][3] + b1;
                if (RELU) {
                    v00 = fmaxf(v00, 0.f); v01 = fmaxf(v01, 0.f);
                    v10 = fmaxf(v10, 0.f); v11 = fmaxf(v11, 0.f);
                }
                if (OUTM == 2) {
                    uint32_t hi0, lo0, hi1, lo1;
                    split_pack(v00, v01, hi0, lo0);
                    split_pack(v10, v11, hi1, lo1);
                    *(uint32_t*)(Chi + (size_t)rg * ldC + c)       = hi0;
                    *(uint32_t*)(Clo + (size_t)rg * ldC + c)       = lo0;
                    *(uint32_t*)(Chi + (size_t)(rg + 8) * ldC + c) = hi1;
                    *(uint32_t*)(Clo + (size_t)(rg + 8) * ldC + c) = lo1;
                } else if (OUTM == 1) {
                    *(uint32_t*)(Chi + (size_t)rg * ldC + c)       = pack_h2(v00, v01);
                    *(uint32_t*)(Chi + (size_t)(rg + 8) * ldC + c) = pack_h2(v10, v11);
                } else {
                    Cf[(size_t)rg * ldC + c]           = v00;
                    Cf[(size_t)rg * ldC + c + 1]       = v01;
                    Cf[(size_t)(rg + 8) * ldC + c]     = v10;
                    Cf[(size_t)(rg + 8) * ldC + c + 1] = v11;
                }
            }
        }
    }
}

// ---------------------------------------------------------------------------
// One merged converter launch: X (hi/lo), W1 (hi/lo), W2 (hi), W3 (hi),
// Wo (hi/lo, N padded 96->128). Weights go to [N][K] K-major.
// ---------------------------------------------------------------------------
#define XC   (ROWS_TOTAL * 32)
#define W1C  (512 * 32)
#define W2C  (512 * 512)
#define W3C  (512 * 512)
#define WOC  (128 * 512)
#define CONVTOT (XC + W1C + W2C + W3C + WOC)

__global__ void conv_all(const float* __restrict__ xk, const float* __restrict__ xn,
                         const float* __restrict__ W1, const float* __restrict__ W2,
                         const float* __restrict__ W3, const float* __restrict__ Wo,
                         __half* __restrict__ Xhi, __half* __restrict__ Xlo,
                         __half* __restrict__ W1thi, __half* __restrict__ W1tlo,
                         __half* __restrict__ W2thi, __half* __restrict__ W3thi,
                         __half* __restrict__ Wothi, __half* __restrict__ Wotlo)
{
    int i = blockIdx.x * 256 + threadIdx.x;
    if (i < XC) {
        int row = i >> 5, c = i & 31;
        float v = (row < BATCH) ? xk[row * 32 + c]
                                : xn[(size_t)(row - BATCH) * 32 + c];
        __half h, l; split_h(v, h, l);
        size_t o = (size_t)row * 32 + c;
        Xhi[o] = h; Xlo[o] = l;
        return;
    }
    i -= XC;
    if (i < W1C) {                       // K=32, N=Npad=512
        int k = i / 512, n = i % 512;
        __half h, l; split_h(W1[k * 512 + n], h, l);
        W1thi[n * 32 + k] = h; W1tlo[n * 32 + k] = l;
        return;
    }
    i -= W1C;
    if (i < W2C) {                       // K=512, N=512, hi only
        int k = i / 512, n = i % 512;
        W2thi[(size_t)n * 512 + k] = __float2half(W2[(size_t)k * 512 + n]);
        return;
    }
    i -= W2C;
    if (i < W3C) {
        int k = i / 512, n = i % 512;
        W3thi[(size_t)n * 512 + k] = __float2half(W3[(size_t)k * 512 + n]);
        return;
    }
    i -= W3C;
    {                                    // Wo: K=512, N=96, Npad=128
        int k = i / 128, n = i % 128;
        float v = (n < 96) ? Wo[(size_t)k * 96 + n] : 0.f;
        __half h, l; split_h(v, h, l);
        Wothi[(size_t)n * 512 + k] = h; Wotlo[(size_t)n * 512 + k] = l;
    }
}

// ---------------------------------------------------------------------------
// z_target assembly + scan (unchanged, fp32-exact)
// ---------------------------------------------------------------------------
__device__ __forceinline__ float2 ffma2(float a, float2 b, float2 c) {
    float2 aa = make_float2(a, a);
    unsigned long long A = *reinterpret_cast<unsigned long long*>(&aa);
    unsigned long long B = *reinterpret_cast<unsigned long long*>(&b);
    unsigned long long C = *reinterpret_cast<unsigned long long*>(&c);
    asm("fma.rn.f32x2 %0, %1, %2, %0;" : "+l"(C) : "l"(A), "l"(B));
    return *reinterpret_cast<float2*>(&C);
}

__global__ void ztarget_kernel(const float* __restrict__ x_next,
                               const float* __restrict__ E_xnext,
                               float* __restrict__ zt)
{
    const size_t idx = (size_t)blockIdx.x * blockDim.x + threadIdx.x;
    const size_t total = (size_t)ROWS_XNEXT * (LATENT_DIM / 4);
    if (idx >= total) return;
    const size_t r = idx >> 5;
    const int    q = (int)(idx & 31);
    float4 v;
    if (q < STATE_DIM / 4)
        v = ((const float4*)x_next)[r * (STATE_DIM / 4) + q];
    else
        v = ((const float4*)E_xnext)[r * (EMBED_DIM / 4) + (q - STATE_DIM / 4)];
    ((float4*)zt)[r * (LATENT_DIM / 4) + q] = v;
}

#define SCAN_ROWS 8
__global__ __launch_bounds__(256)
void scan_kernel(const float* __restrict__ x_k, const float* __restrict__ u_seq,
                 const float* __restrict__ Amat, const float* __restrict__ Bmat,
                 const float* __restrict__ E,
                 float* __restrict__ z_pred, float* __restrict__ x_pred)
{
    __shared__ float zsh[SCAN_ROWS][LATENT_DIM];
    __shared__ float ush[SCAN_ROWS][CONTROL_DIM];

    const int tid = threadIdx.x;
    const int lr  = tid >> 5;
    const int j   = tid & 31;
    const int b   = blockIdx.x * SCAN_ROWS + lr;
    const int d0  = j * 4;

    float4 z;
    if (d0 < STATE_DIM) z = *(const float4*)(x_k + (size_t)b * STATE_DIM + d0);
    else                z = *(const float4*)(E   + (size_t)b * EMBED_DIM + (d0 - STATE_DIM));
    zsh[lr][d0 + 0] = z.x; zsh[lr][d0 + 1] = z.y;
    zsh[lr][d0 + 2] = z.z; zsh[lr][d0 + 3] = z.w;
    if (j < CONTROL_DIM)
        ush[lr][j] = u_seq[((size_t)b * MSEQ + 0) * CONTROL_DIM + j];
    __syncwarp();

    for (int i = 0; i < MSEQ; i++) {
        float2 acc01 = make_float2(0.f, 0.f);
        float2 acc23 = make_float2(0.f, 0.f);

        #pragma unroll
        for (int c = 0; c < CONTROL_DIM; c++) {
            const float uc = ush[lr][c];
            float4 brow = *(const float4*)(Bmat + (size_t)c * LATENT_DIM + d0);
            acc01 = ffma2(uc, make_float2(brow.x, brow.y), acc01);
            acc23 = ffma2(uc, make_float2(brow.z, brow.w), acc23);
        }
        #pragma unroll 32
        for (int k = 0; k < LATENT_DIM; k++) {
            const float zk = zsh[lr][k];
            float4 arow = *(const float4*)(Amat + (size_t)k * LATENT_DIM + d0);
            acc01 = ffma2(zk, make_float2(arow.x, arow.y), acc01);
            acc23 = ffma2(zk, make_float2(arow.z, arow.w), acc23);
        }
        __syncwarp();

        zsh[lr][d0 + 0] = acc01.x; zsh[lr][d0 + 1] = acc01.y;
        zsh[lr][d0 + 2] = acc23.x; zsh[lr][d0 + 3] = acc23.y;
        if (j < CONTROL_DIM && i + 1 < MSEQ)
            ush[lr][j] = u_seq[((size_t)b * MSEQ + (i + 1)) * CONTROL_DIM + j];

        const size_t orow = (size_t)b * MSEQ + i;
        float4 out = make_float4(acc01.x, acc01.y, acc23.x, acc23.y);
        *(float4*)(z_pred + orow * LATENT_DIM + d0) = out;
        if (d0 < STATE_DIM)
            *(float4*)(x_pred + orow * STATE_DIM + d0) = out;
        __syncwarp();
    }
}

// ---------------------------------------------------------------------------
// kernel_launch
// Inputs: 0:x_k 1:u_seq 2:x_next_seq 3:W1 4:b1 5:W2 6:b2 7:W3 8:b3
//         9:Wo 10:bo 11:A 12:Bmat
// ---------------------------------------------------------------------------
extern "C" void kernel_launch(void* const* d_in, const int* in_sizes, int n_in,
                              void* d_out, int out_size)
{
    const float* x_k    = (const float*)d_in[0];
    const float* u_seq  = (const float*)d_in[1];
    const float* x_next = (const float*)d_in[2];
    const float* W1     = (const float*)d_in[3];
    const float* b1     = (const float*)d_in[4];
    const float* W2     = (const float*)d_in[5];
    const float* b2     = (const float*)d_in[6];
    const float* W3     = (const float*)d_in[7];
    const float* b3     = (const float*)d_in[8];
    const float* Wo     = (const float*)d_in[9];
    const float* bo     = (const float*)d_in[10];
    const float* Amat   = (const float*)d_in[11];
    const float* Bmat   = (const float*)d_in[12];

    float* out      = (float*)d_out;
    float* z_pred   = out;
    float* x_pred   = out + (size_t)BATCH * MSEQ * LATENT_DIM;
    float* z_target = x_pred + (size_t)BATCH * MSEQ * STATE_DIM;

    __half *Xhi, *Xlo, *Hahi, *Halo, *Hbhi;
    __half *W1thi, *W1tlo, *W2thi, *W3thi, *Wothi, *Wotlo;
    float* E;
    cudaGetSymbolAddress((void**)&Xhi,  g_Xhi);  cudaGetSymbolAddress((void**)&Xlo,  g_Xlo);
    cudaGetSymbolAddress((void**)&Hahi, g_Hahi); cudaGetSymbolAddress((void**)&Halo, g_Halo);
    cudaGetSymbolAddress((void**)&Hbhi, g_Hbhi);
    cudaGetSymbolAddress((void**)&W1thi, g_W1thi); cudaGetSymbolAddress((void**)&W1tlo, g_W1tlo);
    cudaGetSymbolAddress((void**)&W2thi, g_W2thi);
    cudaGetSymbolAddress((void**)&W3thi, g_W3thi);
    cudaGetSymbolAddress((void**)&Wothi, g_Wothi); cudaGetSymbolAddress((void**)&Wotlo, g_Wotlo);
    cudaGetSymbolAddress((void**)&E, g_E);

    const int SMEM_P3 = 2 * 4 * TILE_B;   // 81920 (3-pass, 2 stages)
    const int SMEM_P1 = 4 * 2 * TILE_B;   // 81920 (1-pass, 4 stages)
    cudaFuncSetAttribute(gemm_mma<1,  2, 3, true,  1>,
                         cudaFuncAttributeMaxDynamicSharedMemorySize, SMEM_P3);
    cudaFuncSetAttribute(gemm_mma<16, 4, 1, true,  1>,
                         cudaFuncAttributeMaxDynamicSharedMemorySize, SMEM_P1);
    cudaFuncSetAttribute(gemm_mma<16, 4, 1, true,  2>,
                         cudaFuncAttributeMaxDynamicSharedMemorySize, SMEM_P1);
    cudaFuncSetAttribute(gemm_mma<16, 2, 3, false, 0>,
                         cudaFuncAttributeMaxDynamicSharedMemorySize, SMEM_P3);

    // all conversions in one launch                            (launch 1)
    conv_all<<<(CONVTOT + 255) / 256, 256>>>(
        x_k, x_next, W1, W2, W3, Wo,
        Xhi, Xlo, W1thi, W1tlo, W2thi, W3thi, Wothi, Wotlo);

    // L1: 3-pass (K=32), single-fp16 out -> Hahi              (launch 2)
    gemm_mma<1, 2, 3, true, 1><<<dim3(4, MTILES), 256, SMEM_P3>>>(
        Xhi, Xlo, 32, W1thi, W1tlo, 32, b1, Hahi, nullptr, nullptr, 512, 512);
    // L2: 1-pass fp16, single out -> Hbhi                     (launch 3)
    gemm_mma<16, 4, 1, true, 1><<<dim3(4, MTILES), 256, SMEM_P1>>>(
        Hahi, nullptr, 512, W2thi, nullptr, 512, b2, Hbhi, nullptr, nullptr, 512, 512);
    // L3: 1-pass fp16, split out -> Hahi/Halo                 (launch 4)
    gemm_mma<16, 4, 1, true, 2><<<dim3(4, MTILES), 256, SMEM_P1>>>(
        Hbhi, nullptr, 512, W3thi, nullptr, 512, b3, Hahi, Halo, nullptr, 512, 512);
    // L4: 3-pass, fp32 out -> E                               (launch 5)
    gemm_mma<16, 2, 3, false, 0><<<dim3(1, MTILES), 256, SMEM_P3>>>(
        Hahi, Halo, 512, Wothi, Wotlo, 512, bo, nullptr, nullptr, E, 96, 96);

    // outputs                                                 (launches 6,7)
    {
        const size_t total = (size_t)ROWS_XNEXT * (LATENT_DIM / 4);
        int nb = (int)((total + 255) / 256);
        ztarget_kernel<<<nb, 256>>>(x_next, E + (size_t)BATCH * EMBED_DIM, z_target);
    }
    scan_kernel<<<BATCH / SCAN_ROWS, 256>>>(x_k, u_seq, Amat, Bmat, E, z_pred, x_pred);

    (void)in_sizes; (void)n_in; (void)out_size;
}